// round 10
// baseline (speedup 1.0000x reference)
#include <cuda_runtime.h>
#include <math.h>

// Problem constants
#define BN 256
#define AN 512
#define TT 21
#define AG 16      // agents per block (8 pairs)
#define NTHR 256
#define EGO_BLKS 256

__device__ int g_mask_is_byte;
__device__ __align__(16) float g_w1t[27 * 32];    // [k][oc] transposed conv1 weights
__device__ __align__(16) float g_w2t[96 * 64];    // [k][oc] transposed conv2 weights
__device__ __align__(16) float g_w3t[192 * 128];  // [k][oc] transposed conv3 weights

// ---------------------------------------------------------------------------
// f32x2 packed helpers (Blackwell dual-fp32 datapath)
// ---------------------------------------------------------------------------
typedef unsigned long long u64;

__device__ __forceinline__ u64 dup2(float a) {
    u64 d; asm("mov.b64 %0,{%1,%1};" : "=l"(d) : "f"(a)); return d;
}
__device__ __forceinline__ void fma2(u64& acc, u64 w, u64 x) {
    asm("fma.rn.f32x2 %0,%1,%2,%0;" : "+l"(acc) : "l"(w), "l"(x));
}
__device__ __forceinline__ float2 unp2(u64 v) {
    float a, b; asm("mov.b64 {%0,%1},%2;" : "=f"(a), "=f"(b) : "l"(v));
    return make_float2(a, b);
}

// conv3 tap pattern: o0: k1*x0+k2*x1 ; o1: k0*x1+k1*x2+k2*x3 ; o2: k0*x3+k1*x4
#define C3(s0, s1, s2, d0, d1, d2, X0, X1, X2, X3, X4) do { \
    fma2(s0, d1, X0); fma2(s0, d2, X1); \
    fma2(s1, d0, X1); fma2(s1, d1, X2); fma2(s1, d2, X3); \
    fma2(s2, d0, X3); fma2(s2, d1, X4); } while (0)

__device__ __forceinline__ int mask_at(const void* p, int idx, int isByte) {
    if (isByte) return ((const unsigned char*)p)[idx] != 0;
    return ((const int*)p)[idx] != 0;
}

// ---------------------------------------------------------------------------
// Prep: weight transposes + mask-dtype detect (block 0). ~3us.
// ---------------------------------------------------------------------------
__global__ void prep_kernel(const unsigned char* __restrict__ vm,
                            const float* __restrict__ w1,
                            const float* __restrict__ w2,
                            const float* __restrict__ w3) {
    int i = blockIdx.x * 256 + threadIdx.x;
    if (i < 864)   { int oc = i / 27,  k = i % 27;  g_w1t[k * 32  + oc] = w1[i]; }
    if (i < 6144)  { int oc = i / 96,  k = i % 96;  g_w2t[k * 64  + oc] = w2[i]; }
    if (i < 24576) { int oc = i / 192, k = i % 192; g_w3t[k * 128 + oc] = w3[i]; }
    if (blockIdx.x == 0) {
        __shared__ int found;
        if (threadIdx.x == 0) found = 0;
        __syncthreads();
        int local = 0;
        for (int j = 0; j < 8; j++) local |= vm[4 * (threadIdx.x * 8 + j) + 1];
        if (local) atomicOr(&found, 1);
        __syncthreads();
        if (threadIdx.x == 0) g_mask_is_byte = found ? 1 : 0;
    }
}

// smem layout (float offsets), all pair-packed float2 (.x even agent, .y odd)
#define XSP_OFF 0        // 8 pairs * 9 ch * 22 t * 2      = 3168  (t20,21 pad)
#define H1P_OFF 3168     // 8 * 11 pos * 32 ic * 2 (posmaj)= 5632  (p10 pad row)
#define H2P_OFF 8800     // 8 * 5 pos * 64 ic * 2 (posmaj) = 5120  (no pad)
#define VA_OFF  13920    // 16 ints
#define SMEM_FLOATS 13936

// ego overlay offsets (within the same dynamic smem; ego uses 2584 floats)
#define EG_XE 0          // 6*128
#define EG_QS 768        // 128
#define EG_KS 896        // 6*128
#define EG_VS 1664       // 6*128
#define EG_AT 2432       // 24
#define EG_OS 2456       // 128

// ---------------------------------------------------------------------------
// Merged kernel: blocks 0..255 = ego attention; blocks 256.. = agent tiles.
// NO static shared memory anywhere (would shrink L1D for all agent CTAs).
// ---------------------------------------------------------------------------
__global__ __launch_bounds__(NTHR, 2) void main_kernel(
    const float* __restrict__ position, const float* __restrict__ heading,
    const float* __restrict__ velocity, const float* __restrict__ shp,
    const int* __restrict__ category, const void* __restrict__ vmask,
    const float* __restrict__ b1, const float* __restrict__ b2,
    const float* __restrict__ b3,
    const float* __restrict__ type_emb, float* __restrict__ out,
    const float* __restrict__ cur,
    const float* __restrict__ se_w, const float* __restrict__ se_b,
    const float* __restrict__ pos_embed, const float* __restrict__ query,
    const float* __restrict__ inW, const float* __restrict__ inB,
    const float* __restrict__ outW, const float* __restrict__ outB)
{
    extern __shared__ float sm[];
    const int tid = threadIdx.x;

    if (blockIdx.x < EGO_BLKS) {
        // ================= ego cross-attention (128 threads) ================
        if (tid >= 128) return;
        const int d = tid;
        const int b = blockIdx.x;
        float* xe = sm + EG_XE;
        float* qs = sm + EG_QS;
        float* ks = sm + EG_KS;
        float* vs = sm + EG_VS;
        float* att = sm + EG_AT;
        float* os = sm + EG_OS;
        #pragma unroll
        for (int s = 0; s < 6; s++) {
            float e = __ldg(&cur[b * 6 + s]);
            xe[s * 128 + d] = e * se_w[s * 128 + d] + se_b[s * 128 + d] + pos_embed[s * 128 + d];
        }
        {
            float acc = inB[d];
            const float* wq = inW + d * 128;
            for (int e = 0; e < 128; e++) acc += __ldg(&query[e]) * wq[e];
            qs[d] = acc;
        }
        __syncthreads();
        {
            float ak[6], av[6];
            float bk = inB[128 + d], bvv = inB[256 + d];
            #pragma unroll
            for (int s = 0; s < 6; s++) { ak[s] = bk; av[s] = bvv; }
            const float* wk = inW + (128 + d) * 128;
            const float* wv = inW + (256 + d) * 128;
            for (int e = 0; e < 128; e++) {
                float wkv = wk[e], wvv = wv[e];
                #pragma unroll
                for (int s = 0; s < 6; s++) {
                    float x = xe[s * 128 + e];
                    ak[s] += wkv * x;
                    av[s] += wvv * x;
                }
            }
            #pragma unroll
            for (int s = 0; s < 6; s++) { ks[s * 128 + d] = ak[s]; vs[s * 128 + d] = av[s]; }
        }
        __syncthreads();
        if (d < 4) {
            int h = d;
            float sc[6], mx = -1e30f;
            #pragma unroll
            for (int s = 0; s < 6; s++) {
                float acc = 0.f;
                #pragma unroll
                for (int j = 0; j < 32; j++) acc += qs[h * 32 + j] * ks[s * 128 + h * 32 + j];
                sc[s] = acc * 0.17677669529663687f;  // 1/sqrt(32)
                mx = fmaxf(mx, sc[s]);
            }
            float sum = 0.f;
            #pragma unroll
            for (int s = 0; s < 6; s++) { sc[s] = expf(sc[s] - mx); sum += sc[s]; }
            float inv = 1.f / sum;
            #pragma unroll
            for (int s = 0; s < 6; s++) att[h * 6 + s] = sc[s] * inv;
        }
        __syncthreads();
        {
            int h = d >> 5;
            float o = 0.f;
            #pragma unroll
            for (int s = 0; s < 6; s++) o += att[h * 6 + s] * vs[s * 128 + d];
            os[d] = o;
        }
        __syncthreads();
        {
            float acc = outB[d];
            const float* w = outW + d * 128;
            for (int e = 0; e < 128; e++) acc += os[e] * w[e];
            int c0 = __ldg(&category[b * AN]);
            out[(size_t)b * AN * 128 + d] = acc + type_emb[c0 * 128 + d];
        }
        return;
    }

    // ======================= agent encoder tile =============================
    const int gbase = (blockIdx.x - EGO_BLKS) * AG;
    const int isByte = g_mask_is_byte;

    // ---- targeted pad zeroing (only slots actually read as pads) ----
    for (int i = tid; i < 72; i += NTHR) {       // XSP t20,t21 per (pair,ch)
        int pair = i / 9, ch = i % 9;
        float* p = sm + XSP_OFF + pair * 396 + ch * 44 + 40;
        p[0] = 0.f; p[1] = 0.f; p[2] = 0.f; p[3] = 0.f;
    }
    for (int i = tid; i < 512; i += NTHR) {      // H1 pad row p=10
        int pair = i >> 6, j = i & 63;
        sm[H1P_OFF + (pair * 11 + 10) * 64 + j] = 0.f;
    }
    if (tid < AG) {
        int g = gbase + tid;
        int any = 0;
        for (int t = 0; t < TT; t++) any |= mask_at(vmask, g * TT + t, isByte);
        ((int*)(sm + VA_OFF))[tid] = any;
    }

    // ---- features: 9 channels x 20 timesteps per agent, pair-packed ----
    for (int idx = tid; idx < AG * 20; idx += NTHR) {
        int a = idx / 20, t = idx % 20;
        int g = gbase + a;
        int pair = a >> 1, lane = a & 1;
        const float* pp = position + (size_t)g * 42;
        const float* vv = velocity + (size_t)g * 42;
        const float* hh = heading  + (size_t)g * 21;
        const float* ss = shp      + (size_t)g * 42;
        int m0 = mask_at(vmask, g * 21 + t,     isByte);
        int m1 = mask_at(vmask, g * 21 + t + 1, isByte);
        float fm = (m0 & m1) ? 1.f : 0.f;
        float p0 = __ldcs(&pp[2 * t]),     p1 = __ldcs(&pp[2 * t + 1]);
        float p2 = __ldcs(&pp[2 * t + 2]), p3 = __ldcs(&pp[2 * t + 3]);
        float v0 = __ldcs(&vv[2 * t]),     v1 = __ldcs(&vv[2 * t + 1]);
        float v2 = __ldcs(&vv[2 * t + 2]), v3 = __ldcs(&vv[2 * t + 3]);
        float h0 = __ldcs(&hh[t]),         h1 = __ldcs(&hh[t + 1]);
        float dx  = fm * (p2 - p0);
        float dy  = fm * (p3 - p1);
        float dvx = fm * (v2 - v0);
        float dvy = fm * (v3 - v1);
        float dh  = fm * (h1 - h0);
        float sv, cv;
        sincosf(dh, &sv, &cv);
        float shx = __ldcs(&ss[2 * t + 2]), shy = __ldcs(&ss[2 * t + 3]);
        float* xr = sm + XSP_OFF + (pair * 9 * 22 + t) * 2 + lane;
        xr[0 * 44] = dx;  xr[1 * 44] = dy;
        xr[2 * 44] = dvx; xr[3 * 44] = dvy;
        xr[4 * 44] = cv;  xr[5 * 44] = sv;
        xr[6 * 44] = shx; xr[7 * 44] = shy;
        xr[8 * 44] = fm;
    }
    __syncthreads();

    // ---- conv1: 9->32, len 20 -> 10, stride 2, relu. (oc, pair)/thread. ----
    {
        const int oc = tid & 31, pair = tid >> 5;
        float wr[27];
        #pragma unroll
        for (int k = 0; k < 27; k++) wr[k] = __ldg(&g_w1t[k * 32 + oc]);  // contiguous
        u64 acc[10];
        u64 bv = dup2(__ldg(&b1[oc]));
        #pragma unroll
        for (int o = 0; o < 10; o++) acc[o] = bv;
        #pragma unroll
        for (int ic = 0; ic < 9; ic++) {
            const ulonglong2* xv = (const ulonglong2*)(sm + XSP_OFF + (pair * 9 + ic) * 44);
            u64 d0 = dup2(wr[ic * 3 + 0]);
            u64 d1 = dup2(wr[ic * 3 + 1]);
            u64 d2 = dup2(wr[ic * 3 + 2]);
            {   // t = 0..11 -> outputs o = 0..4
                ulonglong2 v0 = xv[0], v1 = xv[1], v2 = xv[2],
                           v3 = xv[3], v4 = xv[4], v5 = xv[5];
                u64 x[12] = {v0.x, v0.y, v1.x, v1.y, v2.x, v2.y,
                             v3.x, v3.y, v4.x, v4.y, v5.x, v5.y};
                #pragma unroll
                for (int o = 0; o < 5; o++) {
                    fma2(acc[o], d0, x[2 * o]);
                    fma2(acc[o], d1, x[2 * o + 1]);
                    fma2(acc[o], d2, x[2 * o + 2]);
                }
            }
            {   // t = 10..21 -> outputs o = 5..9 (t20 = zeroed pad)
                ulonglong2 v0 = xv[5], v1 = xv[6], v2 = xv[7],
                           v3 = xv[8], v4 = xv[9], v5 = xv[10];
                u64 x[12] = {v0.x, v0.y, v1.x, v1.y, v2.x, v2.y,
                             v3.x, v3.y, v4.x, v4.y, v5.x, v5.y};
                #pragma unroll
                for (int o = 5; o < 10; o++) {
                    int q = 2 * o - 10;
                    fma2(acc[o], d0, x[q]);
                    fma2(acc[o], d1, x[q + 1]);
                    fma2(acc[o], d2, x[q + 2]);
                }
            }
        }
        #pragma unroll
        for (int o = 0; o < 10; o++) {
            float2 v = unp2(acc[o]);
            *(float2*)(sm + H1P_OFF + ((pair * 11 + o) * 32 + oc) * 2) =
                make_float2(fmaxf(v.x, 0.f), fmaxf(v.y, 0.f));
        }
    }
    __syncthreads();

    // ---- conv2: 32->64, len 10 -> 5, stride 2, relu. 2 oc x 1 pair/thread,
    //      256 active threads. ----
    {
        const int ocg = tid & 31, pair = tid >> 5;   // oc = {2ocg, 2ocg+1}
        float2 b2v = __ldg((const float2*)b2 + ocg);
        u64 A[5], B[5];
        u64 bA = dup2(b2v.x), bB = dup2(b2v.y);
        #pragma unroll
        for (int o = 0; o < 5; o++) { A[o] = bA; B[o] = bB; }
        const float2* w2p = (const float2*)g_w2t;    // row = 32 float2
        #pragma unroll 4
        for (int icp = 0; icp < 16; icp++) {
            const int ic = 2 * icp;
            const float* hb = sm + H1P_OFF + pair * 704 + ic * 2;
            ulonglong2 uv[11];
            #pragma unroll
            for (int p = 0; p < 11; p++)
                uv[p] = *(const ulonglong2*)(hb + p * 64);   // .x = ic, .y = ic+1
            float2 wa0 = __ldg(w2p + (ic * 3 + 0) * 32 + ocg);
            float2 wa1 = __ldg(w2p + (ic * 3 + 1) * 32 + ocg);
            float2 wa2 = __ldg(w2p + (ic * 3 + 2) * 32 + ocg);
            float2 wb0 = __ldg(w2p + (ic * 3 + 3) * 32 + ocg);
            float2 wb1 = __ldg(w2p + (ic * 3 + 4) * 32 + ocg);
            float2 wb2 = __ldg(w2p + (ic * 3 + 5) * 32 + ocg);
            u64 a0 = dup2(wa0.x), a1 = dup2(wa1.x), a2 = dup2(wa2.x);   // ic,  oc0
            u64 b0 = dup2(wa0.y), b1v = dup2(wa1.y), b2w = dup2(wa2.y); // ic,  oc1
            u64 c0 = dup2(wb0.x), c1 = dup2(wb1.x), c2 = dup2(wb2.x);   // ic+1,oc0
            u64 d0 = dup2(wb0.y), d1 = dup2(wb1.y), d2 = dup2(wb2.y);   // ic+1,oc1
            #pragma unroll
            for (int o = 0; o < 5; o++) {
                fma2(A[o], a0, uv[2 * o].x);  fma2(A[o], a1, uv[2 * o + 1].x);  fma2(A[o], a2, uv[2 * o + 2].x);
                fma2(A[o], c0, uv[2 * o].y);  fma2(A[o], c1, uv[2 * o + 1].y);  fma2(A[o], c2, uv[2 * o + 2].y);
                fma2(B[o], b0, uv[2 * o].x);  fma2(B[o], b1v, uv[2 * o + 1].x); fma2(B[o], b2w, uv[2 * o + 2].x);
                fma2(B[o], d0, uv[2 * o].y);  fma2(B[o], d1, uv[2 * o + 1].y);  fma2(B[o], d2, uv[2 * o + 2].y);
            }
        }
        #pragma unroll
        for (int o = 0; o < 5; o++) {
            float2 v0 = unp2(A[o]), v1 = unp2(B[o]);
            *(float4*)(sm + H2P_OFF + (pair * 5 + o) * 128 + 4 * ocg) =
                make_float4(fmaxf(v0.x, 0.f), fmaxf(v0.y, 0.f),
                            fmaxf(v1.x, 0.f), fmaxf(v1.y, 0.f));
        }
    }
    __syncthreads();

    // ---- conv3: 64->128, len 5 -> 3, stride 2. 2 oc x 2 pairs per thread,
    //      256 active threads; direct epilogue. ----
    {
        const int ocg = tid & 63, sg = tid >> 6;     // oc = {2ocg, 2ocg+1}
        const int pr0 = 2 * sg, pr1 = pr0 + 1;
        float2 b3v = __ldg((const float2*)b3 + ocg);
        u64 A0 = dup2(b3v.x), A1 = A0, A2 = A0;      // pair0 oc0
        u64 B0 = dup2(b3v.y), B1 = B0, B2 = B0;      // pair0 oc1
        u64 C0 = A0, C1 = A0, C2 = A0;               // pair1 oc0
        u64 D0 = B0, D1 = B0, D2 = B0;               // pair1 oc1
        const float2* w3p = (const float2*)g_w3t;    // row = 64 float2
        #pragma unroll 4
        for (int icp = 0; icp < 32; icp++) {
            const int ic = 2 * icp;
            const float* h0 = sm + H2P_OFF + (pr0 * 320 + ic) * 2;
            const float* h1b = sm + H2P_OFF + (pr1 * 320 + ic) * 2;
            ulonglong2 u0[5], u1[5];
            #pragma unroll
            for (int p = 0; p < 5; p++) {
                u0[p] = *(const ulonglong2*)(h0 + p * 128);
                u1[p] = *(const ulonglong2*)(h1b + p * 128);
            }
            float2 wa0 = __ldg(w3p + (ic * 3 + 0) * 64 + ocg);
            float2 wa1 = __ldg(w3p + (ic * 3 + 1) * 64 + ocg);
            float2 wa2 = __ldg(w3p + (ic * 3 + 2) * 64 + ocg);
            float2 wb0 = __ldg(w3p + (ic * 3 + 3) * 64 + ocg);
            float2 wb1 = __ldg(w3p + (ic * 3 + 4) * 64 + ocg);
            float2 wb2 = __ldg(w3p + (ic * 3 + 5) * 64 + ocg);
            u64 da0 = dup2(wa0.x), da1 = dup2(wa1.x), da2 = dup2(wa2.x); // ic, oc0
            u64 db0 = dup2(wa0.y), db1 = dup2(wa1.y), db2 = dup2(wa2.y); // ic, oc1
            u64 dc0 = dup2(wb0.x), dc1 = dup2(wb1.x), dc2 = dup2(wb2.x); // ic+1, oc0
            u64 dd0 = dup2(wb0.y), dd1 = dup2(wb1.y), dd2 = dup2(wb2.y); // ic+1, oc1
            C3(A0, A1, A2, da0, da1, da2, u0[0].x, u0[1].x, u0[2].x, u0[3].x, u0[4].x);
            C3(A0, A1, A2, dc0, dc1, dc2, u0[0].y, u0[1].y, u0[2].y, u0[3].y, u0[4].y);
            C3(B0, B1, B2, db0, db1, db2, u0[0].x, u0[1].x, u0[2].x, u0[3].x, u0[4].x);
            C3(B0, B1, B2, dd0, dd1, dd2, u0[0].y, u0[1].y, u0[2].y, u0[3].y, u0[4].y);
            C3(C0, C1, C2, da0, da1, da2, u1[0].x, u1[1].x, u1[2].x, u1[3].x, u1[4].x);
            C3(C0, C1, C2, dc0, dc1, dc2, u1[0].y, u1[1].y, u1[2].y, u1[3].y, u1[4].y);
            C3(D0, D1, D2, db0, db1, db2, u1[0].x, u1[1].x, u1[2].x, u1[3].x, u1[4].x);
            C3(D0, D1, D2, dd0, dd1, dd2, u1[0].y, u1[1].y, u1[2].y, u1[3].y, u1[4].y);
        }
        const int* vA = (const int*)(sm + VA_OFF);
        #define EPI(pb, S0, S1, S2, T0, T1, T2) do { \
            float2 v0 = unp2(S0), v1 = unp2(S1), v2 = unp2(S2); \
            float2 w0 = unp2(T0), w1 = unp2(T1), w2 = unp2(T2); \
            float eX0 = (fmaxf(v0.x,0.f) + fmaxf(v1.x,0.f) + fmaxf(v2.x,0.f)) * (1.f/3.f); \
            float eY0 = (fmaxf(v0.y,0.f) + fmaxf(v1.y,0.f) + fmaxf(v2.y,0.f)) * (1.f/3.f); \
            float eX1 = (fmaxf(w0.x,0.f) + fmaxf(w1.x,0.f) + fmaxf(w2.x,0.f)) * (1.f/3.f); \
            float eY1 = (fmaxf(w0.y,0.f) + fmaxf(w1.y,0.f) + fmaxf(w2.y,0.f)) * (1.f/3.f); \
            int aa = 2 * (pb); \
            if (!vA[aa])     { eX0 = 0.f; eX1 = 0.f; } \
            if (!vA[aa + 1]) { eY0 = 0.f; eY1 = 0.f; } \
            int g0 = gbase + aa, g1 = g0 + 1; \
            if (g0 & (AN - 1)) { \
                int c = __ldg(&category[g0]); \
                float2 te = __ldg((const float2*)type_emb + c * 64 + ocg); \
                __stcs((float2*)(out + (size_t)g0 * 128 + 2 * ocg), make_float2(eX0 + te.x, eX1 + te.y)); \
            } \
            { \
                int c = __ldg(&category[g1]); \
                float2 te = __ldg((const float2*)type_emb + c * 64 + ocg); \
                __stcs((float2*)(out + (size_t)g1 * 128 + 2 * ocg), make_float2(eY0 + te.x, eY1 + te.y)); \
            } \
        } while (0)
        EPI(pr0, A0, A1, A2, B0, B1, B2);
        EPI(pr1, C0, C1, C2, D0, D1, D2);
        #undef EPI
    }
}

// ---------------------------------------------------------------------------
extern "C" void kernel_launch(void* const* d_in, const int* in_sizes, int n_in,
                              void* d_out, int out_size) {
    const float* position  = (const float*)d_in[0];
    const float* heading   = (const float*)d_in[1];
    const float* velocity  = (const float*)d_in[2];
    const float* shp       = (const float*)d_in[3];
    const float* cur       = (const float*)d_in[4];
    const int*   category  = (const int*)d_in[5];
    const void*  vmask     = d_in[6];
    const float* w1        = (const float*)d_in[7];
    const float* b1        = (const float*)d_in[8];
    const float* w2        = (const float*)d_in[9];
    const float* b2        = (const float*)d_in[10];
    const float* w3        = (const float*)d_in[11];
    const float* b3        = (const float*)d_in[12];
    const float* se_w      = (const float*)d_in[13];
    const float* se_b      = (const float*)d_in[14];
    const float* pos_embed = (const float*)d_in[15];
    const float* query     = (const float*)d_in[16];
    const float* inW       = (const float*)d_in[17];
    const float* inB       = (const float*)d_in[18];
    const float* outW      = (const float*)d_in[19];
    const float* outB      = (const float*)d_in[20];
    const float* type_emb  = (const float*)d_in[n_in - 1];
    float* out = (float*)d_out;

    // idempotent, non-stream API; safe under graph capture
    cudaFuncSetAttribute(main_kernel, cudaFuncAttributeMaxDynamicSharedMemorySize,
                         SMEM_FLOATS * (int)sizeof(float));

    prep_kernel<<<96, 256>>>((const unsigned char*)vmask, w1, w2, w3);

    // one merged launch: ego (blocks 0..255) + agent tiles (256..8447)
    main_kernel<<<EGO_BLKS + BN * AN / AG, NTHR, SMEM_FLOATS * sizeof(float)>>>(
        position, heading, velocity, shp, category, vmask,
        b1, b2, b3, type_emb, out,
        cur, se_w, se_b, pos_embed, query, inW, inB, outW, outB);
}

// round 12
// speedup vs baseline: 1.1171x; 1.1171x over previous
#include <cuda_runtime.h>
#include <math.h>

// Problem constants
#define BN 256
#define AN 512
#define TT 21
#define AG 32      // agents per block (16 pairs)
#define NTHR 256
#define EGO_BLKS 256

__device__ int g_mask_is_byte;
__device__ __align__(16) float g_w1t[27 * 32];    // [k][oc] transposed conv1 weights
__device__ __align__(16) float g_w2t[96 * 64];    // [k][oc] transposed conv2 weights
__device__ __align__(16) float g_w3t[192 * 128];  // [k][oc] transposed conv3 weights

// ---------------------------------------------------------------------------
// f32x2 packed helpers (Blackwell dual-fp32 datapath)
// ---------------------------------------------------------------------------
typedef unsigned long long u64;

__device__ __forceinline__ u64 dup2(float a) {
    u64 d; asm("mov.b64 %0,{%1,%1};" : "=l"(d) : "f"(a)); return d;
}
__device__ __forceinline__ void fma2(u64& acc, u64 w, u64 x) {
    asm("fma.rn.f32x2 %0,%1,%2,%0;" : "+l"(acc) : "l"(w), "l"(x));
}
__device__ __forceinline__ float2 unp2(u64 v) {
    float a, b; asm("mov.b64 {%0,%1},%2;" : "=f"(a), "=f"(b) : "l"(v));
    return make_float2(a, b);
}

// conv3 tap pattern: o0: k1*x0+k2*x1 ; o1: k0*x1+k1*x2+k2*x3 ; o2: k0*x3+k1*x4
#define C3(s0, s1, s2, d0, d1, d2, X0, X1, X2, X3, X4) do { \
    fma2(s0, d1, X0); fma2(s0, d2, X1); \
    fma2(s1, d0, X1); fma2(s1, d1, X2); fma2(s1, d2, X3); \
    fma2(s2, d0, X3); fma2(s2, d1, X4); } while (0)

__device__ __forceinline__ int mask_at(const void* p, int idx, int isByte) {
    if (isByte) return ((const unsigned char*)p)[idx] != 0;
    return ((const int*)p)[idx] != 0;
}

// ---------------------------------------------------------------------------
// Prep: weight transposes + mask-dtype detect (block 0). ~3us.
// ---------------------------------------------------------------------------
__global__ void prep_kernel(const unsigned char* __restrict__ vm,
                            const float* __restrict__ w1,
                            const float* __restrict__ w2,
                            const float* __restrict__ w3) {
    int i = blockIdx.x * 256 + threadIdx.x;
    if (i < 864)   { int oc = i / 27,  k = i % 27;  g_w1t[k * 32  + oc] = w1[i]; }
    if (i < 6144)  { int oc = i / 96,  k = i % 96;  g_w2t[k * 64  + oc] = w2[i]; }
    if (i < 24576) { int oc = i / 192, k = i % 192; g_w3t[k * 128 + oc] = w3[i]; }
    if (blockIdx.x == 0) {
        __shared__ int found;
        if (threadIdx.x == 0) found = 0;
        __syncthreads();
        int local = 0;
        for (int j = 0; j < 8; j++) local |= vm[4 * (threadIdx.x * 8 + j) + 1];
        if (local) atomicOr(&found, 1);
        __syncthreads();
        if (threadIdx.x == 0) g_mask_is_byte = found ? 1 : 0;
    }
}

// smem layout (float offsets), all pair-packed float2 (.x even agent, .y odd)
#define XSP_OFF 0        // 16 pairs * 9 ch * 22 t * 2      = 6336  (t20,21 pad)
#define H1P_OFF 6336     // 16 * 11 pos * 32 ic * 2 (posmaj)= 11264 (p10 pad row)
#define H2P_OFF 17600    // 16 * 5 pos * 64 ic * 2 (posmaj) = 10240 (no pad)
#define VA_OFF  27840    // 32 ints
#define SMEM_FLOATS 27872

// ego overlay offsets (within the same dynamic smem; ego uses 2584 floats)
#define EG_XE 0
#define EG_QS 768
#define EG_KS 896
#define EG_VS 1664
#define EG_AT 2432
#define EG_OS 2456

// ---------------------------------------------------------------------------
// Merged kernel: blocks 0..255 = ego attention; blocks 256.. = agent tiles
// (32 agents each). No static smem.
// ---------------------------------------------------------------------------
__global__ __launch_bounds__(NTHR, 2) void main_kernel(
    const float* __restrict__ position, const float* __restrict__ heading,
    const float* __restrict__ velocity, const float* __restrict__ shp,
    const int* __restrict__ category, const void* __restrict__ vmask,
    const float* __restrict__ b1, const float* __restrict__ b2,
    const float* __restrict__ b3,
    const float* __restrict__ type_emb, float* __restrict__ out,
    const float* __restrict__ cur,
    const float* __restrict__ se_w, const float* __restrict__ se_b,
    const float* __restrict__ pos_embed, const float* __restrict__ query,
    const float* __restrict__ inW, const float* __restrict__ inB,
    const float* __restrict__ outW, const float* __restrict__ outB)
{
    extern __shared__ float sm[];
    const int tid = threadIdx.x;

    if (blockIdx.x < EGO_BLKS) {
        // ================= ego cross-attention (128 threads) ================
        if (tid >= 128) return;
        const int d = tid;
        const int b = blockIdx.x;
        float* xe = sm + EG_XE;
        float* qs = sm + EG_QS;
        float* ks = sm + EG_KS;
        float* vs = sm + EG_VS;
        float* att = sm + EG_AT;
        float* os = sm + EG_OS;
        #pragma unroll
        for (int s = 0; s < 6; s++) {
            float e = __ldg(&cur[b * 6 + s]);
            xe[s * 128 + d] = e * se_w[s * 128 + d] + se_b[s * 128 + d] + pos_embed[s * 128 + d];
        }
        {
            float acc = inB[d];
            const float* wq = inW + d * 128;
            for (int e = 0; e < 128; e++) acc += __ldg(&query[e]) * wq[e];
            qs[d] = acc;
        }
        __syncthreads();
        {
            float ak[6], av[6];
            float bk = inB[128 + d], bvv = inB[256 + d];
            #pragma unroll
            for (int s = 0; s < 6; s++) { ak[s] = bk; av[s] = bvv; }
            const float* wk = inW + (128 + d) * 128;
            const float* wv = inW + (256 + d) * 128;
            for (int e = 0; e < 128; e++) {
                float wkv = wk[e], wvv = wv[e];
                #pragma unroll
                for (int s = 0; s < 6; s++) {
                    float x = xe[s * 128 + e];
                    ak[s] += wkv * x;
                    av[s] += wvv * x;
                }
            }
            #pragma unroll
            for (int s = 0; s < 6; s++) { ks[s * 128 + d] = ak[s]; vs[s * 128 + d] = av[s]; }
        }
        __syncthreads();
        if (d < 4) {
            int h = d;
            float sc[6], mx = -1e30f;
            #pragma unroll
            for (int s = 0; s < 6; s++) {
                float acc = 0.f;
                #pragma unroll
                for (int j = 0; j < 32; j++) acc += qs[h * 32 + j] * ks[s * 128 + h * 32 + j];
                sc[s] = acc * 0.17677669529663687f;  // 1/sqrt(32)
                mx = fmaxf(mx, sc[s]);
            }
            float sum = 0.f;
            #pragma unroll
            for (int s = 0; s < 6; s++) { sc[s] = expf(sc[s] - mx); sum += sc[s]; }
            float inv = 1.f / sum;
            #pragma unroll
            for (int s = 0; s < 6; s++) att[h * 6 + s] = sc[s] * inv;
        }
        __syncthreads();
        {
            int h = d >> 5;
            float o = 0.f;
            #pragma unroll
            for (int s = 0; s < 6; s++) o += att[h * 6 + s] * vs[s * 128 + d];
            os[d] = o;
        }
        __syncthreads();
        {
            float acc = outB[d];
            const float* w = outW + d * 128;
            for (int e = 0; e < 128; e++) acc += os[e] * w[e];
            int c0 = __ldg(&category[b * AN]);
            out[(size_t)b * AN * 128 + d] = acc + type_emb[c0 * 128 + d];
        }
        return;
    }

    // ======================= agent encoder tile (32 agents) =================
    const int gbase = (blockIdx.x - EGO_BLKS) * AG;
    const int isByte = g_mask_is_byte;

    // ---- targeted pad zeroing ----
    for (int i = tid; i < 144; i += NTHR) {      // XSP t20,t21 per (pair,ch)
        int pair = i / 9, ch = i % 9;
        float* p = sm + XSP_OFF + pair * 396 + ch * 44 + 40;
        p[0] = 0.f; p[1] = 0.f; p[2] = 0.f; p[3] = 0.f;
    }
    for (int i = tid; i < 1024; i += NTHR) {     // H1 pad row p=10
        int pair = i >> 6, j = i & 63;
        sm[H1P_OFF + (pair * 11 + 10) * 64 + j] = 0.f;
    }
    if (tid < AG) {
        int g = gbase + tid;
        int any = 0;
        for (int t = 0; t < TT; t++) any |= mask_at(vmask, g * TT + t, isByte);
        ((int*)(sm + VA_OFF))[tid] = any;
    }

    // ---- features: 9 channels x 20 timesteps per agent, pair-packed ----
    for (int idx = tid; idx < AG * 20; idx += NTHR) {
        int a = idx / 20, t = idx % 20;
        int g = gbase + a;
        int pair = a >> 1, lane = a & 1;
        const float* pp = position + (size_t)g * 42;
        const float* vv = velocity + (size_t)g * 42;
        const float* hh = heading  + (size_t)g * 21;
        const float* ss = shp      + (size_t)g * 42;
        int m0 = mask_at(vmask, g * 21 + t,     isByte);
        int m1 = mask_at(vmask, g * 21 + t + 1, isByte);
        float fm = (m0 & m1) ? 1.f : 0.f;
        float p0 = __ldcs(&pp[2 * t]),     p1 = __ldcs(&pp[2 * t + 1]);
        float p2 = __ldcs(&pp[2 * t + 2]), p3 = __ldcs(&pp[2 * t + 3]);
        float v0 = __ldcs(&vv[2 * t]),     v1 = __ldcs(&vv[2 * t + 1]);
        float v2 = __ldcs(&vv[2 * t + 2]), v3 = __ldcs(&vv[2 * t + 3]);
        float h0 = __ldcs(&hh[t]),         h1 = __ldcs(&hh[t + 1]);
        float dx  = fm * (p2 - p0);
        float dy  = fm * (p3 - p1);
        float dvx = fm * (v2 - v0);
        float dvy = fm * (v3 - v1);
        float dh  = fm * (h1 - h0);
        float sv, cv;
        sincosf(dh, &sv, &cv);
        float shx = __ldcs(&ss[2 * t + 2]), shy = __ldcs(&ss[2 * t + 3]);
        float* xr = sm + XSP_OFF + (pair * 9 * 22 + t) * 2 + lane;
        xr[0 * 44] = dx;  xr[1 * 44] = dy;
        xr[2 * 44] = dvx; xr[3 * 44] = dvy;
        xr[4 * 44] = cv;  xr[5 * 44] = sv;
        xr[6 * 44] = shx; xr[7 * 44] = shy;
        xr[8 * 44] = fm;
    }
    __syncthreads();

    // ---- conv1: 9->32, len 20 -> 10, stride 2, relu.
    //      (oc, 2 sequential pairs)/thread; weights loaded once. ----
    {
        const int oc = tid & 31, pair0 = tid >> 5;
        float wr[27];
        #pragma unroll
        for (int k = 0; k < 27; k++) wr[k] = __ldg(&g_w1t[k * 32 + oc]);
        u64 bv = dup2(__ldg(&b1[oc]));
        #pragma unroll
        for (int pass = 0; pass < 2; pass++) {
            const int pair = pair0 + 8 * pass;
            u64 acc[10];
            #pragma unroll
            for (int o = 0; o < 10; o++) acc[o] = bv;
            #pragma unroll
            for (int ic = 0; ic < 9; ic++) {
                const ulonglong2* xv = (const ulonglong2*)(sm + XSP_OFF + (pair * 9 + ic) * 44);
                u64 d0 = dup2(wr[ic * 3 + 0]);
                u64 d1 = dup2(wr[ic * 3 + 1]);
                u64 d2 = dup2(wr[ic * 3 + 2]);
                {   // t = 0..11 -> outputs o = 0..4
                    ulonglong2 v0 = xv[0], v1 = xv[1], v2 = xv[2],
                               v3 = xv[3], v4 = xv[4], v5 = xv[5];
                    u64 x[12] = {v0.x, v0.y, v1.x, v1.y, v2.x, v2.y,
                                 v3.x, v3.y, v4.x, v4.y, v5.x, v5.y};
                    #pragma unroll
                    for (int o = 0; o < 5; o++) {
                        fma2(acc[o], d0, x[2 * o]);
                        fma2(acc[o], d1, x[2 * o + 1]);
                        fma2(acc[o], d2, x[2 * o + 2]);
                    }
                }
                {   // t = 10..21 -> outputs o = 5..9 (t20 = zeroed pad)
                    ulonglong2 v0 = xv[5], v1 = xv[6], v2 = xv[7],
                               v3 = xv[8], v4 = xv[9], v5 = xv[10];
                    u64 x[12] = {v0.x, v0.y, v1.x, v1.y, v2.x, v2.y,
                                 v3.x, v3.y, v4.x, v4.y, v5.x, v5.y};
                    #pragma unroll
                    for (int o = 5; o < 10; o++) {
                        int q = 2 * o - 10;
                        fma2(acc[o], d0, x[q]);
                        fma2(acc[o], d1, x[q + 1]);
                        fma2(acc[o], d2, x[q + 2]);
                    }
                }
            }
            #pragma unroll
            for (int o = 0; o < 10; o++) {
                float2 v = unp2(acc[o]);
                *(float2*)(sm + H1P_OFF + ((pair * 11 + o) * 32 + oc) * 2) =
                    make_float2(fmaxf(v.x, 0.f), fmaxf(v.y, 0.f));
            }
        }
    }
    __syncthreads();

    // ---- conv2: 32->64, len 10 -> 5, stride 2, relu.
    //      2 oc x 2 pairs per thread (pairs pr, pr+8); 256 active threads. ---
    {
        const int ocg = tid & 31, pairg = tid >> 5;   // oc = {2ocg, 2ocg+1}
        const int pr0 = pairg, pr1 = pairg + 8;
        float2 b2v = __ldg((const float2*)b2 + ocg);
        u64 A[5], B[5], C[5], D[5];
        u64 bA = dup2(b2v.x), bB = dup2(b2v.y);
        #pragma unroll
        for (int o = 0; o < 5; o++) { A[o] = bA; B[o] = bB; C[o] = bA; D[o] = bB; }
        const float2* w2p = (const float2*)g_w2t;    // row = 32 float2
        #pragma unroll 2
        for (int icp = 0; icp < 16; icp++) {
            const int ic = 2 * icp;
            float2 wa0 = __ldg(w2p + (ic * 3 + 0) * 32 + ocg);
            float2 wa1 = __ldg(w2p + (ic * 3 + 1) * 32 + ocg);
            float2 wa2 = __ldg(w2p + (ic * 3 + 2) * 32 + ocg);
            float2 wb0 = __ldg(w2p + (ic * 3 + 3) * 32 + ocg);
            float2 wb1 = __ldg(w2p + (ic * 3 + 4) * 32 + ocg);
            float2 wb2 = __ldg(w2p + (ic * 3 + 5) * 32 + ocg);
            u64 a0 = dup2(wa0.x), a1 = dup2(wa1.x), a2 = dup2(wa2.x);   // ic,  oc0
            u64 b0 = dup2(wa0.y), b1v = dup2(wa1.y), b2w = dup2(wa2.y); // ic,  oc1
            u64 c0 = dup2(wb0.x), c1 = dup2(wb1.x), c2 = dup2(wb2.x);   // ic+1,oc0
            u64 d0 = dup2(wb0.y), d1 = dup2(wb1.y), d2 = dup2(wb2.y);   // ic+1,oc1
            {   // pair pr0 -> A,B
                const float* hb = sm + H1P_OFF + pr0 * 704 + ic * 2;
                ulonglong2 uv[11];
                #pragma unroll
                for (int p = 0; p < 11; p++)
                    uv[p] = *(const ulonglong2*)(hb + p * 64);
                #pragma unroll
                for (int o = 0; o < 5; o++) {
                    fma2(A[o], a0, uv[2*o].x);  fma2(A[o], a1, uv[2*o+1].x);  fma2(A[o], a2, uv[2*o+2].x);
                    fma2(A[o], c0, uv[2*o].y);  fma2(A[o], c1, uv[2*o+1].y);  fma2(A[o], c2, uv[2*o+2].y);
                    fma2(B[o], b0, uv[2*o].x);  fma2(B[o], b1v, uv[2*o+1].x); fma2(B[o], b2w, uv[2*o+2].x);
                    fma2(B[o], d0, uv[2*o].y);  fma2(B[o], d1, uv[2*o+1].y);  fma2(B[o], d2, uv[2*o+2].y);
                }
            }
            {   // pair pr1 -> C,D
                const float* hb = sm + H1P_OFF + pr1 * 704 + ic * 2;
                ulonglong2 uv[11];
                #pragma unroll
                for (int p = 0; p < 11; p++)
                    uv[p] = *(const ulonglong2*)(hb + p * 64);
                #pragma unroll
                for (int o = 0; o < 5; o++) {
                    fma2(C[o], a0, uv[2*o].x);  fma2(C[o], a1, uv[2*o+1].x);  fma2(C[o], a2, uv[2*o+2].x);
                    fma2(C[o], c0, uv[2*o].y);  fma2(C[o], c1, uv[2*o+1].y);  fma2(C[o], c2, uv[2*o+2].y);
                    fma2(D[o], b0, uv[2*o].x);  fma2(D[o], b1v, uv[2*o+1].x); fma2(D[o], b2w, uv[2*o+2].x);
                    fma2(D[o], d0, uv[2*o].y);  fma2(D[o], d1, uv[2*o+1].y);  fma2(D[o], d2, uv[2*o+2].y);
                }
            }
        }
        #pragma unroll
        for (int o = 0; o < 5; o++) {
            float2 v0 = unp2(A[o]), v1 = unp2(B[o]);
            *(float4*)(sm + H2P_OFF + (pr0 * 5 + o) * 128 + 4 * ocg) =
                make_float4(fmaxf(v0.x,0.f), fmaxf(v0.y,0.f), fmaxf(v1.x,0.f), fmaxf(v1.y,0.f));
            float2 v2 = unp2(C[o]), v3 = unp2(D[o]);
            *(float4*)(sm + H2P_OFF + (pr1 * 5 + o) * 128 + 4 * ocg) =
                make_float4(fmaxf(v2.x,0.f), fmaxf(v2.y,0.f), fmaxf(v3.x,0.f), fmaxf(v3.y,0.f));
        }
    }
    __syncthreads();

    // ---- conv3: 64->128, len 5 -> 3, stride 2. 2 oc x 4 pairs per thread;
    //      256 active threads; direct epilogue. ----
    {
        const int ocg = tid & 63, sg = tid >> 6;     // oc = {2ocg, 2ocg+1}, sg 0-3
        float2 b3v = __ldg((const float2*)b3 + ocg);
        u64 P[4][3], Q[4][3];
        {
            u64 bx = dup2(b3v.x), by = dup2(b3v.y);
            #pragma unroll
            for (int j = 0; j < 4; j++) {
                P[j][0] = bx; P[j][1] = bx; P[j][2] = bx;
                Q[j][0] = by; Q[j][1] = by; Q[j][2] = by;
            }
        }
        const float2* w3p = (const float2*)g_w3t;    // row = 64 float2
        #pragma unroll 2
        for (int icp = 0; icp < 32; icp++) {
            const int ic = 2 * icp;
            float2 wa0 = __ldg(w3p + (ic * 3 + 0) * 64 + ocg);
            float2 wa1 = __ldg(w3p + (ic * 3 + 1) * 64 + ocg);
            float2 wa2 = __ldg(w3p + (ic * 3 + 2) * 64 + ocg);
            float2 wb0 = __ldg(w3p + (ic * 3 + 3) * 64 + ocg);
            float2 wb1 = __ldg(w3p + (ic * 3 + 4) * 64 + ocg);
            float2 wb2 = __ldg(w3p + (ic * 3 + 5) * 64 + ocg);
            u64 da0 = dup2(wa0.x), da1 = dup2(wa1.x), da2 = dup2(wa2.x); // ic, oc0
            u64 db0 = dup2(wa0.y), db1 = dup2(wa1.y), db2 = dup2(wa2.y); // ic, oc1
            u64 dc0 = dup2(wb0.x), dc1 = dup2(wb1.x), dc2 = dup2(wb2.x); // ic+1, oc0
            u64 dd0 = dup2(wb0.y), dd1 = dup2(wb1.y), dd2 = dup2(wb2.y); // ic+1, oc1
            #pragma unroll
            for (int j = 0; j < 4; j++) {
                const int pr = 4 * sg + j;
                const float* hb = sm + H2P_OFF + (pr * 320 + ic) * 2;
                ulonglong2 u0 = *(const ulonglong2*)(hb);
                ulonglong2 u1 = *(const ulonglong2*)(hb + 128);
                ulonglong2 u2 = *(const ulonglong2*)(hb + 256);
                ulonglong2 u3 = *(const ulonglong2*)(hb + 384);
                ulonglong2 u4 = *(const ulonglong2*)(hb + 512);
                C3(P[j][0], P[j][1], P[j][2], da0, da1, da2, u0.x, u1.x, u2.x, u3.x, u4.x);
                C3(P[j][0], P[j][1], P[j][2], dc0, dc1, dc2, u0.y, u1.y, u2.y, u3.y, u4.y);
                C3(Q[j][0], Q[j][1], Q[j][2], db0, db1, db2, u0.x, u1.x, u2.x, u3.x, u4.x);
                C3(Q[j][0], Q[j][1], Q[j][2], dd0, dd1, dd2, u0.y, u1.y, u2.y, u3.y, u4.y);
            }
        }
        const int* vA = (const int*)(sm + VA_OFF);
        #pragma unroll
        for (int j = 0; j < 4; j++) {
            const int pr = 4 * sg + j;
            float2 v0 = unp2(P[j][0]), v1 = unp2(P[j][1]), v2 = unp2(P[j][2]);
            float2 w0 = unp2(Q[j][0]), w1 = unp2(Q[j][1]), w2 = unp2(Q[j][2]);
            float eX0 = (fmaxf(v0.x,0.f) + fmaxf(v1.x,0.f) + fmaxf(v2.x,0.f)) * (1.f/3.f);
            float eY0 = (fmaxf(v0.y,0.f) + fmaxf(v1.y,0.f) + fmaxf(v2.y,0.f)) * (1.f/3.f);
            float eX1 = (fmaxf(w0.x,0.f) + fmaxf(w1.x,0.f) + fmaxf(w2.x,0.f)) * (1.f/3.f);
            float eY1 = (fmaxf(w0.y,0.f) + fmaxf(w1.y,0.f) + fmaxf(w2.y,0.f)) * (1.f/3.f);
            int aa = 2 * pr;
            if (!vA[aa])     { eX0 = 0.f; eX1 = 0.f; }
            if (!vA[aa + 1]) { eY0 = 0.f; eY1 = 0.f; }
            int g0 = gbase + aa, g1 = g0 + 1;
            if (g0 & (AN - 1)) {
                int c = __ldg(&category[g0]);
                float2 te = __ldg((const float2*)type_emb + c * 64 + ocg);
                __stcs((float2*)(out + (size_t)g0 * 128 + 2 * ocg),
                       make_float2(eX0 + te.x, eX1 + te.y));
            }
            {
                int c = __ldg(&category[g1]);
                float2 te = __ldg((const float2*)type_emb + c * 64 + ocg);
                __stcs((float2*)(out + (size_t)g1 * 128 + 2 * ocg),
                       make_float2(eY0 + te.x, eY1 + te.y));
            }
        }
    }
}

// ---------------------------------------------------------------------------
extern "C" void kernel_launch(void* const* d_in, const int* in_sizes, int n_in,
                              void* d_out, int out_size) {
    const float* position  = (const float*)d_in[0];
    const float* heading   = (const float*)d_in[1];
    const float* velocity  = (const float*)d_in[2];
    const float* shp       = (const float*)d_in[3];
    const float* cur       = (const float*)d_in[4];
    const int*   category  = (const int*)d_in[5];
    const void*  vmask     = d_in[6];
    const float* w1        = (const float*)d_in[7];
    const float* b1        = (const float*)d_in[8];
    const float* w2        = (const float*)d_in[9];
    const float* b2        = (const float*)d_in[10];
    const float* w3        = (const float*)d_in[11];
    const float* b3        = (const float*)d_in[12];
    const float* se_w      = (const float*)d_in[13];
    const float* se_b      = (const float*)d_in[14];
    const float* pos_embed = (const float*)d_in[15];
    const float* query     = (const float*)d_in[16];
    const float* inW       = (const float*)d_in[17];
    const float* inB       = (const float*)d_in[18];
    const float* outW      = (const float*)d_in[19];
    const float* outB      = (const float*)d_in[20];
    const float* type_emb  = (const float*)d_in[n_in - 1];
    float* out = (float*)d_out;

    // idempotent, non-stream API; safe under graph capture
    cudaFuncSetAttribute(main_kernel, cudaFuncAttributeMaxDynamicSharedMemorySize,
                         SMEM_FLOATS * (int)sizeof(float));

    prep_kernel<<<96, 256>>>((const unsigned char*)vmask, w1, w2, w3);

    // one merged launch: ego (blocks 0..255) + agent tiles (256..4351)
    main_kernel<<<EGO_BLKS + BN * AN / AG, NTHR, SMEM_FLOATS * sizeof(float)>>>(
        position, heading, velocity, shp, category, vmask,
        b1, b2, b3, type_emb, out,
        cur, se_w, se_b, pos_embed, query, inW, inB, outW, outB);
}

// round 13
// speedup vs baseline: 1.1211x; 1.0036x over previous
#include <cuda_runtime.h>
#include <math.h>

// Problem constants
#define BN 256
#define AN 512
#define TT 21
#define AG 32      // agents per block (16 pairs)
#define NTHR 256
#define EGO_BLKS 256

__device__ int g_mask_is_byte;
__device__ __align__(16) float g_w1t[27 * 32];    // [k][oc] transposed conv1 weights
__device__ __align__(16) float g_w2t[96 * 64];    // [k][oc] transposed conv2 weights
__device__ __align__(16) float g_w3t[192 * 128];  // [k][oc] transposed conv3 weights

// ---------------------------------------------------------------------------
// f32x2 packed helpers (Blackwell dual-fp32 datapath)
// ---------------------------------------------------------------------------
typedef unsigned long long u64;

__device__ __forceinline__ u64 dup2(float a) {
    u64 d; asm("mov.b64 %0,{%1,%1};" : "=l"(d) : "f"(a)); return d;
}
__device__ __forceinline__ void fma2(u64& acc, u64 w, u64 x) {
    asm("fma.rn.f32x2 %0,%1,%2,%0;" : "+l"(acc) : "l"(w), "l"(x));
}
__device__ __forceinline__ float2 unp2(u64 v) {
    float a, b; asm("mov.b64 {%0,%1},%2;" : "=f"(a), "=f"(b) : "l"(v));
    return make_float2(a, b);
}

// conv3 tap pattern: o0: k1*x0+k2*x1 ; o1: k0*x1+k1*x2+k2*x3 ; o2: k0*x3+k1*x4
#define C3(s0, s1, s2, d0, d1, d2, X0, X1, X2, X3, X4) do { \
    fma2(s0, d1, X0); fma2(s0, d2, X1); \
    fma2(s1, d0, X1); fma2(s1, d1, X2); fma2(s1, d2, X3); \
    fma2(s2, d0, X3); fma2(s2, d1, X4); } while (0)

__device__ __forceinline__ int mask_at(const void* p, int idx, int isByte) {
    if (isByte) return ((const unsigned char*)p)[idx] != 0;
    return ((const int*)p)[idx] != 0;
}

// ---------------------------------------------------------------------------
// Prep: weight transposes + mask-dtype detect (block 0). ~3us.
// ---------------------------------------------------------------------------
__global__ void prep_kernel(const unsigned char* __restrict__ vm,
                            const float* __restrict__ w1,
                            const float* __restrict__ w2,
                            const float* __restrict__ w3) {
    int i = blockIdx.x * 256 + threadIdx.x;
    if (i < 864)   { int oc = i / 27,  k = i % 27;  g_w1t[k * 32  + oc] = w1[i]; }
    if (i < 6144)  { int oc = i / 96,  k = i % 96;  g_w2t[k * 64  + oc] = w2[i]; }
    if (i < 24576) { int oc = i / 192, k = i % 192; g_w3t[k * 128 + oc] = w3[i]; }
    if (blockIdx.x == 0) {
        __shared__ int found;
        if (threadIdx.x == 0) found = 0;
        __syncthreads();
        int local = 0;
        for (int j = 0; j < 8; j++) local |= vm[4 * (threadIdx.x * 8 + j) + 1];
        if (local) atomicOr(&found, 1);
        __syncthreads();
        if (threadIdx.x == 0) g_mask_is_byte = found ? 1 : 0;
    }
}

// smem layout (float offsets), all pair-packed float2 (.x even agent, .y odd)
#define XSP_OFF 0        // 16 pairs * 9 ch * 22 t * 2      = 6336  (t20,21 pad)
#define H1P_OFF 6336     // 16 * 11 pos * 32 ic * 2 (posmaj)= 11264 (p10 pad row)
#define H2P_OFF 17600    // 16 * 5 pos * 64 ic * 2 (posmaj) = 10240 (no pad)
#define VA_OFF  27840    // 32 ints
#define SMEM_FLOATS 27872

// ego overlay offsets (within the same dynamic smem; ego uses 2584 floats)
#define EG_XE 0
#define EG_QS 768
#define EG_KS 896
#define EG_VS 1664
#define EG_AT 2432
#define EG_OS 2456

// ---------------------------------------------------------------------------
// Merged kernel: blocks 0..255 = ego attention; blocks 256.. = agent tiles
// (32 agents each). No static smem.
// ---------------------------------------------------------------------------
__global__ __launch_bounds__(NTHR, 2) void main_kernel(
    const float* __restrict__ position, const float* __restrict__ heading,
    const float* __restrict__ velocity, const float* __restrict__ shp,
    const int* __restrict__ category, const void* __restrict__ vmask,
    const float* __restrict__ b1, const float* __restrict__ b2,
    const float* __restrict__ b3,
    const float* __restrict__ type_emb, float* __restrict__ out,
    const float* __restrict__ cur,
    const float* __restrict__ se_w, const float* __restrict__ se_b,
    const float* __restrict__ pos_embed, const float* __restrict__ query,
    const float* __restrict__ inW, const float* __restrict__ inB,
    const float* __restrict__ outW, const float* __restrict__ outB)
{
    extern __shared__ float sm[];
    const int tid = threadIdx.x;

    if (blockIdx.x < EGO_BLKS) {
        // ================= ego cross-attention (128 threads) ================
        if (tid >= 128) return;
        const int d = tid;
        const int b = blockIdx.x;
        float* xe = sm + EG_XE;
        float* qs = sm + EG_QS;
        float* ks = sm + EG_KS;
        float* vs = sm + EG_VS;
        float* att = sm + EG_AT;
        float* os = sm + EG_OS;
        #pragma unroll
        for (int s = 0; s < 6; s++) {
            float e = __ldg(&cur[b * 6 + s]);
            xe[s * 128 + d] = e * se_w[s * 128 + d] + se_b[s * 128 + d] + pos_embed[s * 128 + d];
        }
        {
            float acc = inB[d];
            const float* wq = inW + d * 128;
            for (int e = 0; e < 128; e++) acc += __ldg(&query[e]) * wq[e];
            qs[d] = acc;
        }
        __syncthreads();
        {
            float ak[6], av[6];
            float bk = inB[128 + d], bvv = inB[256 + d];
            #pragma unroll
            for (int s = 0; s < 6; s++) { ak[s] = bk; av[s] = bvv; }
            const float* wk = inW + (128 + d) * 128;
            const float* wv = inW + (256 + d) * 128;
            for (int e = 0; e < 128; e++) {
                float wkv = wk[e], wvv = wv[e];
                #pragma unroll
                for (int s = 0; s < 6; s++) {
                    float x = xe[s * 128 + e];
                    ak[s] += wkv * x;
                    av[s] += wvv * x;
                }
            }
            #pragma unroll
            for (int s = 0; s < 6; s++) { ks[s * 128 + d] = ak[s]; vs[s * 128 + d] = av[s]; }
        }
        __syncthreads();
        if (d < 4) {
            int h = d;
            float sc[6], mx = -1e30f;
            #pragma unroll
            for (int s = 0; s < 6; s++) {
                float acc = 0.f;
                #pragma unroll
                for (int j = 0; j < 32; j++) acc += qs[h * 32 + j] * ks[s * 128 + h * 32 + j];
                sc[s] = acc * 0.17677669529663687f;  // 1/sqrt(32)
                mx = fmaxf(mx, sc[s]);
            }
            float sum = 0.f;
            #pragma unroll
            for (int s = 0; s < 6; s++) { sc[s] = expf(sc[s] - mx); sum += sc[s]; }
            float inv = 1.f / sum;
            #pragma unroll
            for (int s = 0; s < 6; s++) att[h * 6 + s] = sc[s] * inv;
        }
        __syncthreads();
        {
            int h = d >> 5;
            float o = 0.f;
            #pragma unroll
            for (int s = 0; s < 6; s++) o += att[h * 6 + s] * vs[s * 128 + d];
            os[d] = o;
        }
        __syncthreads();
        {
            float acc = outB[d];
            const float* w = outW + d * 128;
            for (int e = 0; e < 128; e++) acc += os[e] * w[e];
            int c0 = __ldg(&category[b * AN]);
            out[(size_t)b * AN * 128 + d] = acc + type_emb[c0 * 128 + d];
        }
        return;
    }

    // ======================= agent encoder tile (32 agents) =================
    const int gbase = (blockIdx.x - EGO_BLKS) * AG;
    const int isByte = g_mask_is_byte;

    // ---- targeted pad zeroing ----
    for (int i = tid; i < 144; i += NTHR) {      // XSP t20,t21 per (pair,ch)
        int pair = i / 9, ch = i % 9;
        float* p = sm + XSP_OFF + pair * 396 + ch * 44 + 40;
        p[0] = 0.f; p[1] = 0.f; p[2] = 0.f; p[3] = 0.f;
    }
    for (int i = tid; i < 1024; i += NTHR) {     // H1 pad row p=10
        int pair = i >> 6, j = i & 63;
        sm[H1P_OFF + (pair * 11 + 10) * 64 + j] = 0.f;
    }
    if (tid < AG) {
        int g = gbase + tid;
        int any = 0;
        for (int t = 0; t < TT; t++) any |= mask_at(vmask, g * TT + t, isByte);
        ((int*)(sm + VA_OFF))[tid] = any;
    }

    // ---- features: 9 channels x 20 timesteps per agent, pair-packed ----
    for (int idx = tid; idx < AG * 20; idx += NTHR) {
        int a = idx / 20, t = idx % 20;
        int g = gbase + a;
        int pair = a >> 1, lane = a & 1;
        const float2* pf = (const float2*)(position + (size_t)g * 42);
        const float2* vf = (const float2*)(velocity + (size_t)g * 42);
        const float2* sf = (const float2*)(shp      + (size_t)g * 42);
        const float*  hh = heading + (size_t)g * 21;
        int m0 = mask_at(vmask, g * 21 + t,     isByte);
        int m1 = mask_at(vmask, g * 21 + t + 1, isByte);
        float fm = (m0 & m1) ? 1.f : 0.f;
        float2 pa = __ldcs(pf + t), pb = __ldcs(pf + t + 1);
        float2 va = __ldcs(vf + t), vb = __ldcs(vf + t + 1);
        float2 sb = __ldcs(sf + t + 1);
        float h0 = __ldcs(&hh[t]), h1 = __ldcs(&hh[t + 1]);
        float dx  = fm * (pb.x - pa.x);
        float dy  = fm * (pb.y - pa.y);
        float dvx = fm * (vb.x - va.x);
        float dvy = fm * (vb.y - va.y);
        float dh  = fm * (h1 - h0);
        float sv, cv;
        __sincosf(dh, &sv, &cv);     // |dh| small; abs err ~4e-7 << 1e-3 budget
        float* xr = sm + XSP_OFF + (pair * 9 * 22 + t) * 2 + lane;
        xr[0 * 44] = dx;   xr[1 * 44] = dy;
        xr[2 * 44] = dvx;  xr[3 * 44] = dvy;
        xr[4 * 44] = cv;   xr[5 * 44] = sv;
        xr[6 * 44] = sb.x; xr[7 * 44] = sb.y;
        xr[8 * 44] = fm;
    }
    __syncthreads();

    // ---- conv1: 9->32, len 20 -> 10, stride 2, relu.
    //      (oc, 2 sequential pairs)/thread; weights loaded once. ----
    {
        const int oc = tid & 31, pair0 = tid >> 5;
        float wr[27];
        #pragma unroll
        for (int k = 0; k < 27; k++) wr[k] = __ldg(&g_w1t[k * 32 + oc]);
        u64 bv = dup2(__ldg(&b1[oc]));
        #pragma unroll
        for (int pass = 0; pass < 2; pass++) {
            const int pair = pair0 + 8 * pass;
            u64 acc[10];
            #pragma unroll
            for (int o = 0; o < 10; o++) acc[o] = bv;
            #pragma unroll
            for (int ic = 0; ic < 9; ic++) {
                const ulonglong2* xv = (const ulonglong2*)(sm + XSP_OFF + (pair * 9 + ic) * 44);
                u64 d0 = dup2(wr[ic * 3 + 0]);
                u64 d1 = dup2(wr[ic * 3 + 1]);
                u64 d2 = dup2(wr[ic * 3 + 2]);
                {   // t = 0..11 -> outputs o = 0..4
                    ulonglong2 v0 = xv[0], v1 = xv[1], v2 = xv[2],
                               v3 = xv[3], v4 = xv[4], v5 = xv[5];
                    u64 x[12] = {v0.x, v0.y, v1.x, v1.y, v2.x, v2.y,
                                 v3.x, v3.y, v4.x, v4.y, v5.x, v5.y};
                    #pragma unroll
                    for (int o = 0; o < 5; o++) {
                        fma2(acc[o], d0, x[2 * o]);
                        fma2(acc[o], d1, x[2 * o + 1]);
                        fma2(acc[o], d2, x[2 * o + 2]);
                    }
                }
                {   // t = 10..21 -> outputs o = 5..9 (t20 = zeroed pad)
                    ulonglong2 v0 = xv[5], v1 = xv[6], v2 = xv[7],
                               v3 = xv[8], v4 = xv[9], v5 = xv[10];
                    u64 x[12] = {v0.x, v0.y, v1.x, v1.y, v2.x, v2.y,
                                 v3.x, v3.y, v4.x, v4.y, v5.x, v5.y};
                    #pragma unroll
                    for (int o = 5; o < 10; o++) {
                        int q = 2 * o - 10;
                        fma2(acc[o], d0, x[q]);
                        fma2(acc[o], d1, x[q + 1]);
                        fma2(acc[o], d2, x[q + 2]);
                    }
                }
            }
            #pragma unroll
            for (int o = 0; o < 10; o++) {
                float2 v = unp2(acc[o]);
                *(float2*)(sm + H1P_OFF + ((pair * 11 + o) * 32 + oc) * 2) =
                    make_float2(fmaxf(v.x, 0.f), fmaxf(v.y, 0.f));
            }
        }
    }
    __syncthreads();

    // ---- conv2: 32->64, len 10 -> 5, stride 2, relu.
    //      2 oc x 2 pairs per thread (pairs pr, pr+8); 256 active threads. ---
    {
        const int ocg = tid & 31, pairg = tid >> 5;   // oc = {2ocg, 2ocg+1}
        const int pr0 = pairg, pr1 = pairg + 8;
        float2 b2v = __ldg((const float2*)b2 + ocg);
        u64 A[5], B[5], C[5], D[5];
        u64 bA = dup2(b2v.x), bB = dup2(b2v.y);
        #pragma unroll
        for (int o = 0; o < 5; o++) { A[o] = bA; B[o] = bB; C[o] = bA; D[o] = bB; }
        const float2* w2p = (const float2*)g_w2t;    // row = 32 float2
        #pragma unroll 2
        for (int icp = 0; icp < 16; icp++) {
            const int ic = 2 * icp;
            float2 wa0 = __ldg(w2p + (ic * 3 + 0) * 32 + ocg);
            float2 wa1 = __ldg(w2p + (ic * 3 + 1) * 32 + ocg);
            float2 wa2 = __ldg(w2p + (ic * 3 + 2) * 32 + ocg);
            float2 wb0 = __ldg(w2p + (ic * 3 + 3) * 32 + ocg);
            float2 wb1 = __ldg(w2p + (ic * 3 + 4) * 32 + ocg);
            float2 wb2 = __ldg(w2p + (ic * 3 + 5) * 32 + ocg);
            u64 a0 = dup2(wa0.x), a1 = dup2(wa1.x), a2 = dup2(wa2.x);   // ic,  oc0
            u64 b0 = dup2(wa0.y), b1v = dup2(wa1.y), b2w = dup2(wa2.y); // ic,  oc1
            u64 c0 = dup2(wb0.x), c1 = dup2(wb1.x), c2 = dup2(wb2.x);   // ic+1,oc0
            u64 d0 = dup2(wb0.y), d1 = dup2(wb1.y), d2 = dup2(wb2.y);   // ic+1,oc1
            {   // pair pr0 -> A,B
                const float* hb = sm + H1P_OFF + pr0 * 704 + ic * 2;
                ulonglong2 uv[11];
                #pragma unroll
                for (int p = 0; p < 11; p++)
                    uv[p] = *(const ulonglong2*)(hb + p * 64);
                #pragma unroll
                for (int o = 0; o < 5; o++) {
                    fma2(A[o], a0, uv[2*o].x);  fma2(A[o], a1, uv[2*o+1].x);  fma2(A[o], a2, uv[2*o+2].x);
                    fma2(A[o], c0, uv[2*o].y);  fma2(A[o], c1, uv[2*o+1].y);  fma2(A[o], c2, uv[2*o+2].y);
                    fma2(B[o], b0, uv[2*o].x);  fma2(B[o], b1v, uv[2*o+1].x); fma2(B[o], b2w, uv[2*o+2].x);
                    fma2(B[o], d0, uv[2*o].y);  fma2(B[o], d1, uv[2*o+1].y);  fma2(B[o], d2, uv[2*o+2].y);
                }
            }
            {   // pair pr1 -> C,D
                const float* hb = sm + H1P_OFF + pr1 * 704 + ic * 2;
                ulonglong2 uv[11];
                #pragma unroll
                for (int p = 0; p < 11; p++)
                    uv[p] = *(const ulonglong2*)(hb + p * 64);
                #pragma unroll
                for (int o = 0; o < 5; o++) {
                    fma2(C[o], a0, uv[2*o].x);  fma2(C[o], a1, uv[2*o+1].x);  fma2(C[o], a2, uv[2*o+2].x);
                    fma2(C[o], c0, uv[2*o].y);  fma2(C[o], c1, uv[2*o+1].y);  fma2(C[o], c2, uv[2*o+2].y);
                    fma2(D[o], b0, uv[2*o].x);  fma2(D[o], b1v, uv[2*o+1].x); fma2(D[o], b2w, uv[2*o+2].x);
                    fma2(D[o], d0, uv[2*o].y);  fma2(D[o], d1, uv[2*o+1].y);  fma2(D[o], d2, uv[2*o+2].y);
                }
            }
        }
        #pragma unroll
        for (int o = 0; o < 5; o++) {
            float2 v0 = unp2(A[o]), v1 = unp2(B[o]);
            *(float4*)(sm + H2P_OFF + (pr0 * 5 + o) * 128 + 4 * ocg) =
                make_float4(fmaxf(v0.x,0.f), fmaxf(v0.y,0.f), fmaxf(v1.x,0.f), fmaxf(v1.y,0.f));
            float2 v2 = unp2(C[o]), v3 = unp2(D[o]);
            *(float4*)(sm + H2P_OFF + (pr1 * 5 + o) * 128 + 4 * ocg) =
                make_float4(fmaxf(v2.x,0.f), fmaxf(v2.y,0.f), fmaxf(v3.x,0.f), fmaxf(v3.y,0.f));
        }
    }
    __syncthreads();

    // ---- conv3: 64->128, len 5 -> 3, stride 2. 2 oc x 4 pairs per thread;
    //      256 active threads; direct epilogue. ----
    {
        const int ocg = tid & 63, sg = tid >> 6;     // oc = {2ocg, 2ocg+1}, sg 0-3
        float2 b3v = __ldg((const float2*)b3 + ocg);
        u64 P[4][3], Q[4][3];
        {
            u64 bx = dup2(b3v.x), by = dup2(b3v.y);
            #pragma unroll
            for (int j = 0; j < 4; j++) {
                P[j][0] = bx; P[j][1] = bx; P[j][2] = bx;
                Q[j][0] = by; Q[j][1] = by; Q[j][2] = by;
            }
        }
        const float2* w3p = (const float2*)g_w3t;    // row = 64 float2
        #pragma unroll 2
        for (int icp = 0; icp < 32; icp++) {
            const int ic = 2 * icp;
            float2 wa0 = __ldg(w3p + (ic * 3 + 0) * 64 + ocg);
            float2 wa1 = __ldg(w3p + (ic * 3 + 1) * 64 + ocg);
            float2 wa2 = __ldg(w3p + (ic * 3 + 2) * 64 + ocg);
            float2 wb0 = __ldg(w3p + (ic * 3 + 3) * 64 + ocg);
            float2 wb1 = __ldg(w3p + (ic * 3 + 4) * 64 + ocg);
            float2 wb2 = __ldg(w3p + (ic * 3 + 5) * 64 + ocg);
            u64 da0 = dup2(wa0.x), da1 = dup2(wa1.x), da2 = dup2(wa2.x); // ic, oc0
            u64 db0 = dup2(wa0.y), db1 = dup2(wa1.y), db2 = dup2(wa2.y); // ic, oc1
            u64 dc0 = dup2(wb0.x), dc1 = dup2(wb1.x), dc2 = dup2(wb2.x); // ic+1, oc0
            u64 dd0 = dup2(wb0.y), dd1 = dup2(wb1.y), dd2 = dup2(wb2.y); // ic+1, oc1
            #pragma unroll
            for (int j = 0; j < 4; j++) {
                const int pr = 4 * sg + j;
                const float* hb = sm + H2P_OFF + (pr * 320 + ic) * 2;
                ulonglong2 u0 = *(const ulonglong2*)(hb);
                ulonglong2 u1 = *(const ulonglong2*)(hb + 128);
                ulonglong2 u2 = *(const ulonglong2*)(hb + 256);
                ulonglong2 u3 = *(const ulonglong2*)(hb + 384);
                ulonglong2 u4 = *(const ulonglong2*)(hb + 512);
                C3(P[j][0], P[j][1], P[j][2], da0, da1, da2, u0.x, u1.x, u2.x, u3.x, u4.x);
                C3(P[j][0], P[j][1], P[j][2], dc0, dc1, dc2, u0.y, u1.y, u2.y, u3.y, u4.y);
                C3(Q[j][0], Q[j][1], Q[j][2], db0, db1, db2, u0.x, u1.x, u2.x, u3.x, u4.x);
                C3(Q[j][0], Q[j][1], Q[j][2], dd0, dd1, dd2, u0.y, u1.y, u2.y, u3.y, u4.y);
            }
        }
        const int* vA = (const int*)(sm + VA_OFF);
        #pragma unroll
        for (int j = 0; j < 4; j++) {
            const int pr = 4 * sg + j;
            float2 v0 = unp2(P[j][0]), v1 = unp2(P[j][1]), v2 = unp2(P[j][2]);
            float2 w0 = unp2(Q[j][0]), w1 = unp2(Q[j][1]), w2 = unp2(Q[j][2]);
            float eX0 = (fmaxf(v0.x,0.f) + fmaxf(v1.x,0.f) + fmaxf(v2.x,0.f)) * (1.f/3.f);
            float eY0 = (fmaxf(v0.y,0.f) + fmaxf(v1.y,0.f) + fmaxf(v2.y,0.f)) * (1.f/3.f);
            float eX1 = (fmaxf(w0.x,0.f) + fmaxf(w1.x,0.f) + fmaxf(w2.x,0.f)) * (1.f/3.f);
            float eY1 = (fmaxf(w0.y,0.f) + fmaxf(w1.y,0.f) + fmaxf(w2.y,0.f)) * (1.f/3.f);
            int aa = 2 * pr;
            if (!vA[aa])     { eX0 = 0.f; eX1 = 0.f; }
            if (!vA[aa + 1]) { eY0 = 0.f; eY1 = 0.f; }
            int g0 = gbase + aa, g1 = g0 + 1;
            if (g0 & (AN - 1)) {
                int c = __ldg(&category[g0]);
                float2 te = __ldg((const float2*)type_emb + c * 64 + ocg);
                __stcs((float2*)(out + (size_t)g0 * 128 + 2 * ocg),
                       make_float2(eX0 + te.x, eX1 + te.y));
            }
            {
                int c = __ldg(&category[g1]);
                float2 te = __ldg((const float2*)type_emb + c * 64 + ocg);
                __stcs((float2*)(out + (size_t)g1 * 128 + 2 * ocg),
                       make_float2(eY0 + te.x, eY1 + te.y));
            }
        }
    }
}

// ---------------------------------------------------------------------------
extern "C" void kernel_launch(void* const* d_in, const int* in_sizes, int n_in,
                              void* d_out, int out_size) {
    const float* position  = (const float*)d_in[0];
    const float* heading   = (const float*)d_in[1];
    const float* velocity  = (const float*)d_in[2];
    const float* shp       = (const float*)d_in[3];
    const float* cur       = (const float*)d_in[4];
    const int*   category  = (const int*)d_in[5];
    const void*  vmask     = d_in[6];
    const float* w1        = (const float*)d_in[7];
    const float* b1        = (const float*)d_in[8];
    const float* w2        = (const float*)d_in[9];
    const float* b2        = (const float*)d_in[10];
    const float* w3        = (const float*)d_in[11];
    const float* b3        = (const float*)d_in[12];
    const float* se_w      = (const float*)d_in[13];
    const float* se_b      = (const float*)d_in[14];
    const float* pos_embed = (const float*)d_in[15];
    const float* query     = (const float*)d_in[16];
    const float* inW       = (const float*)d_in[17];
    const float* inB       = (const float*)d_in[18];
    const float* outW      = (const float*)d_in[19];
    const float* outB      = (const float*)d_in[20];
    const float* type_emb  = (const float*)d_in[n_in - 1];
    float* out = (float*)d_out;

    // idempotent, non-stream API; safe under graph capture
    cudaFuncSetAttribute(main_kernel, cudaFuncAttributeMaxDynamicSharedMemorySize,
                         SMEM_FLOATS * (int)sizeof(float));

    prep_kernel<<<96, 256>>>((const unsigned char*)vmask, w1, w2, w3);

    // one merged launch: ego (blocks 0..255) + agent tiles (256..4351)
    main_kernel<<<EGO_BLKS + BN * AN / AG, NTHR, SMEM_FLOATS * sizeof(float)>>>(
        position, heading, velocity, shp, category, vmask,
        b1, b2, b3, type_emb, out,
        cur, se_w, se_b, pos_embed, query, inW, inB, outW, outB);
}

// round 14
// speedup vs baseline: 1.2228x; 1.0907x over previous
#include <cuda_runtime.h>
#include <math.h>

// Problem constants
#define BN 256
#define AN 512
#define TT 21
#define AG 32      // agents per block (16 pairs)
#define NTHR 256
#define EGO_BLKS 256

__device__ int g_mask_is_byte;
__device__ __align__(16) float g_w1t[27 * 32];    // [k][oc] transposed conv1 weights
__device__ __align__(16) float g_w2t[96 * 64];    // [k][oc] transposed conv2 weights
__device__ __align__(16) float g_w3t[192 * 128];  // [k][oc] transposed conv3 weights
__device__ __align__(16) float g_inWt[128 * 384]; // [e][row] transposed in_proj_w
__device__ __align__(16) float g_outWt[128 * 128];// [e][row] transposed out_proj_w

// ---------------------------------------------------------------------------
// f32x2 packed helpers (Blackwell dual-fp32 datapath)
// ---------------------------------------------------------------------------
typedef unsigned long long u64;

__device__ __forceinline__ u64 dup2(float a) {
    u64 d; asm("mov.b64 %0,{%1,%1};" : "=l"(d) : "f"(a)); return d;
}
__device__ __forceinline__ void fma2(u64& acc, u64 w, u64 x) {
    asm("fma.rn.f32x2 %0,%1,%2,%0;" : "+l"(acc) : "l"(w), "l"(x));
}
__device__ __forceinline__ float2 unp2(u64 v) {
    float a, b; asm("mov.b64 {%0,%1},%2;" : "=f"(a), "=f"(b) : "l"(v));
    return make_float2(a, b);
}

// conv3 tap pattern: o0: k1*x0+k2*x1 ; o1: k0*x1+k1*x2+k2*x3 ; o2: k0*x3+k1*x4
#define C3(s0, s1, s2, d0, d1, d2, X0, X1, X2, X3, X4) do { \
    fma2(s0, d1, X0); fma2(s0, d2, X1); \
    fma2(s1, d0, X1); fma2(s1, d1, X2); fma2(s1, d2, X3); \
    fma2(s2, d0, X3); fma2(s2, d1, X4); } while (0)

__device__ __forceinline__ int mask_at(const void* p, int idx, int isByte) {
    if (isByte) return ((const unsigned char*)p)[idx] != 0;
    return ((const int*)p)[idx] != 0;
}

// ---------------------------------------------------------------------------
// Prep: weight transposes + mask-dtype detect (block 0). ~4us.
// ---------------------------------------------------------------------------
__global__ void prep_kernel(const unsigned char* __restrict__ vm,
                            const float* __restrict__ w1,
                            const float* __restrict__ w2,
                            const float* __restrict__ w3,
                            const float* __restrict__ inW,
                            const float* __restrict__ outW) {
    int i = blockIdx.x * 256 + threadIdx.x;
    if (i < 864)   { int oc = i / 27,  k = i % 27;  g_w1t[k * 32  + oc] = w1[i]; }
    if (i < 6144)  { int oc = i / 96,  k = i % 96;  g_w2t[k * 64  + oc] = w2[i]; }
    if (i < 24576) { int oc = i / 192, k = i % 192; g_w3t[k * 128 + oc] = w3[i]; }
    if (i < 49152) { int row = i / 128, e = i % 128; g_inWt[e * 384 + row] = inW[i]; }
    if (i < 16384) { int row = i / 128, e = i % 128; g_outWt[e * 128 + row] = outW[i]; }
    if (blockIdx.x == 0) {
        __shared__ int found;
        if (threadIdx.x == 0) found = 0;
        __syncthreads();
        int local = 0;
        for (int j = 0; j < 8; j++) local |= vm[4 * (threadIdx.x * 8 + j) + 1];
        if (local) atomicOr(&found, 1);
        __syncthreads();
        if (threadIdx.x == 0) g_mask_is_byte = found ? 1 : 0;
    }
}

// smem layout (float offsets), all pair-packed float2 (.x even agent, .y odd)
#define XSP_OFF 0        // 16 pairs * 9 ch * 22 t * 2      = 6336  (t20,21 pad)
#define H1P_OFF 6336     // 16 * 11 pos * 32 ic * 2 (posmaj)= 11264 (p10 pad row)
#define H2P_OFF 17600    // 16 * 5 pos * 64 ic * 2 (posmaj) = 10240 (no pad)
#define VA_OFF  27840    // 32 ints
#define SMEM_FLOATS 27872

// ego overlay offsets (within the same dynamic smem; ego uses 2584 floats)
#define EG_XE 0
#define EG_QS 768
#define EG_KS 896
#define EG_VS 1664
#define EG_AT 2432
#define EG_OS 2456

// ---------------------------------------------------------------------------
// Merged kernel: blocks 0..255 = ego attention; blocks 256.. = agent tiles
// (32 agents each). No static smem.
// ---------------------------------------------------------------------------
__global__ __launch_bounds__(NTHR, 2) void main_kernel(
    const float* __restrict__ position, const float* __restrict__ heading,
    const float* __restrict__ velocity, const float* __restrict__ shp,
    const int* __restrict__ category, const void* __restrict__ vmask,
    const float* __restrict__ b1, const float* __restrict__ b2,
    const float* __restrict__ b3,
    const float* __restrict__ type_emb, float* __restrict__ out,
    const float* __restrict__ cur,
    const float* __restrict__ se_w, const float* __restrict__ se_b,
    const float* __restrict__ pos_embed, const float* __restrict__ query,
    const float* __restrict__ inB, const float* __restrict__ outB)
{
    extern __shared__ float sm[];
    const int tid = threadIdx.x;

    if (blockIdx.x < EGO_BLKS) {
        // ================= ego cross-attention (128 threads) ================
        if (tid >= 128) return;
        const int d = tid;
        const int b = blockIdx.x;
        float* xe = sm + EG_XE;
        float* qs = sm + EG_QS;
        float* ks = sm + EG_KS;
        float* vs = sm + EG_VS;
        float* att = sm + EG_AT;
        float* os = sm + EG_OS;
        #pragma unroll
        for (int s = 0; s < 6; s++) {
            float e = __ldg(&cur[b * 6 + s]);
            xe[s * 128 + d] = e * se_w[s * 128 + d] + se_b[s * 128 + d] + pos_embed[s * 128 + d];
        }
        {
            // q[d] = sum_e query[e] * inW[d][e]  (lane-contiguous transposed reads)
            float acc = inB[d];
            for (int e = 0; e < 128; e++)
                acc += __ldg(&query[e]) * __ldg(&g_inWt[e * 384 + d]);
            qs[d] = acc;
        }
        __syncthreads();
        {
            float ak[6], av[6];
            float bk = inB[128 + d], bvv = inB[256 + d];
            #pragma unroll
            for (int s = 0; s < 6; s++) { ak[s] = bk; av[s] = bvv; }
            for (int e = 0; e < 128; e++) {
                float wkv = __ldg(&g_inWt[e * 384 + 128 + d]);   // Wk[d][e]
                float wvv = __ldg(&g_inWt[e * 384 + 256 + d]);   // Wv[d][e]
                #pragma unroll
                for (int s = 0; s < 6; s++) {
                    float x = xe[s * 128 + e];
                    ak[s] += wkv * x;
                    av[s] += wvv * x;
                }
            }
            #pragma unroll
            for (int s = 0; s < 6; s++) { ks[s * 128 + d] = ak[s]; vs[s * 128 + d] = av[s]; }
        }
        __syncthreads();
        if (d < 4) {
            int h = d;
            float sc[6], mx = -1e30f;
            #pragma unroll
            for (int s = 0; s < 6; s++) {
                float acc = 0.f;
                #pragma unroll
                for (int j = 0; j < 32; j++) acc += qs[h * 32 + j] * ks[s * 128 + h * 32 + j];
                sc[s] = acc * 0.17677669529663687f;  // 1/sqrt(32)
                mx = fmaxf(mx, sc[s]);
            }
            float sum = 0.f;
            #pragma unroll
            for (int s = 0; s < 6; s++) { sc[s] = expf(sc[s] - mx); sum += sc[s]; }
            float inv = 1.f / sum;
            #pragma unroll
            for (int s = 0; s < 6; s++) att[h * 6 + s] = sc[s] * inv;
        }
        __syncthreads();
        {
            int h = d >> 5;
            float o = 0.f;
            #pragma unroll
            for (int s = 0; s < 6; s++) o += att[h * 6 + s] * vs[s * 128 + d];
            os[d] = o;
        }
        __syncthreads();
        {
            float acc = outB[d];
            for (int e = 0; e < 128; e++)
                acc += os[e] * __ldg(&g_outWt[e * 128 + d]);     // outW[d][e]
            int c0 = __ldg(&category[b * AN]);
            out[(size_t)b * AN * 128 + d] = acc + type_emb[c0 * 128 + d];
        }
        return;
    }

    // ======================= agent encoder tile (32 agents) =================
    const int gbase = (blockIdx.x - EGO_BLKS) * AG;
    const int isByte = g_mask_is_byte;

    // ---- targeted pad zeroing ----
    for (int i = tid; i < 144; i += NTHR) {      // XSP t20,t21 per (pair,ch)
        int pair = i / 9, ch = i % 9;
        float* p = sm + XSP_OFF + pair * 396 + ch * 44 + 40;
        p[0] = 0.f; p[1] = 0.f; p[2] = 0.f; p[3] = 0.f;
    }
    for (int i = tid; i < 1024; i += NTHR) {     // H1 pad row p=10
        int pair = i >> 6, j = i & 63;
        sm[H1P_OFF + (pair * 11 + 10) * 64 + j] = 0.f;
    }
    if (tid < AG) {
        int g = gbase + tid;
        int any = 0;
        for (int t = 0; t < TT; t++) any |= mask_at(vmask, g * TT + t, isByte);
        ((int*)(sm + VA_OFF))[tid] = any;
    }

    // ---- features: 9 channels x 20 timesteps per agent, pair-packed ----
    for (int idx = tid; idx < AG * 20; idx += NTHR) {
        int a = idx / 20, t = idx % 20;
        int g = gbase + a;
        int pair = a >> 1, lane = a & 1;
        const float2* pf = (const float2*)(position + (size_t)g * 42);
        const float2* vf = (const float2*)(velocity + (size_t)g * 42);
        const float2* sf = (const float2*)(shp      + (size_t)g * 42);
        const float*  hh = heading + (size_t)g * 21;
        int m0 = mask_at(vmask, g * 21 + t,     isByte);
        int m1 = mask_at(vmask, g * 21 + t + 1, isByte);
        float fm = (m0 & m1) ? 1.f : 0.f;
        float2 pa = __ldcs(pf + t), pb = __ldcs(pf + t + 1);
        float2 va = __ldcs(vf + t), vb = __ldcs(vf + t + 1);
        float2 sb = __ldcs(sf + t + 1);
        float h0 = __ldcs(&hh[t]), h1 = __ldcs(&hh[t + 1]);
        float dx  = fm * (pb.x - pa.x);
        float dy  = fm * (pb.y - pa.y);
        float dvx = fm * (vb.x - va.x);
        float dvy = fm * (vb.y - va.y);
        float dh  = fm * (h1 - h0);
        float sv, cv;
        __sincosf(dh, &sv, &cv);     // |dh| small; abs err ~4e-7 << 1e-3 budget
        float* xr = sm + XSP_OFF + (pair * 9 * 22 + t) * 2 + lane;
        xr[0 * 44] = dx;   xr[1 * 44] = dy;
        xr[2 * 44] = dvx;  xr[3 * 44] = dvy;
        xr[4 * 44] = cv;   xr[5 * 44] = sv;
        xr[6 * 44] = sb.x; xr[7 * 44] = sb.y;
        xr[8 * 44] = fm;
    }
    __syncthreads();

    // ---- conv1: 9->32, len 20 -> 10, stride 2, relu.
    //      (oc, 2 sequential pairs)/thread; weights loaded once. ----
    {
        const int oc = tid & 31, pair0 = tid >> 5;
        float wr[27];
        #pragma unroll
        for (int k = 0; k < 27; k++) wr[k] = __ldg(&g_w1t[k * 32 + oc]);
        u64 bv = dup2(__ldg(&b1[oc]));
        #pragma unroll
        for (int pass = 0; pass < 2; pass++) {
            const int pair = pair0 + 8 * pass;
            u64 acc[10];
            #pragma unroll
            for (int o = 0; o < 10; o++) acc[o] = bv;
            #pragma unroll
            for (int ic = 0; ic < 9; ic++) {
                const ulonglong2* xv = (const ulonglong2*)(sm + XSP_OFF + (pair * 9 + ic) * 44);
                u64 d0 = dup2(wr[ic * 3 + 0]);
                u64 d1 = dup2(wr[ic * 3 + 1]);
                u64 d2 = dup2(wr[ic * 3 + 2]);
                {   // t = 0..11 -> outputs o = 0..4
                    ulonglong2 v0 = xv[0], v1 = xv[1], v2 = xv[2],
                               v3 = xv[3], v4 = xv[4], v5 = xv[5];
                    u64 x[12] = {v0.x, v0.y, v1.x, v1.y, v2.x, v2.y,
                                 v3.x, v3.y, v4.x, v4.y, v5.x, v5.y};
                    #pragma unroll
                    for (int o = 0; o < 5; o++) {
                        fma2(acc[o], d0, x[2 * o]);
                        fma2(acc[o], d1, x[2 * o + 1]);
                        fma2(acc[o], d2, x[2 * o + 2]);
                    }
                }
                {   // t = 10..21 -> outputs o = 5..9 (t20 = zeroed pad)
                    ulonglong2 v0 = xv[5], v1 = xv[6], v2 = xv[7],
                               v3 = xv[8], v4 = xv[9], v5 = xv[10];
                    u64 x[12] = {v0.x, v0.y, v1.x, v1.y, v2.x, v2.y,
                                 v3.x, v3.y, v4.x, v4.y, v5.x, v5.y};
                    #pragma unroll
                    for (int o = 5; o < 10; o++) {
                        int q = 2 * o - 10;
                        fma2(acc[o], d0, x[q]);
                        fma2(acc[o], d1, x[q + 1]);
                        fma2(acc[o], d2, x[q + 2]);
                    }
                }
            }
            #pragma unroll
            for (int o = 0; o < 10; o++) {
                float2 v = unp2(acc[o]);
                *(float2*)(sm + H1P_OFF + ((pair * 11 + o) * 32 + oc) * 2) =
                    make_float2(fmaxf(v.x, 0.f), fmaxf(v.y, 0.f));
            }
        }
    }
    __syncthreads();

    // ---- conv2: 32->64, len 10 -> 5, stride 2, relu.
    //      2 oc x 2 pairs per thread (pairs pr, pr+8); 256 active threads. ---
    {
        const int ocg = tid & 31, pairg = tid >> 5;   // oc = {2ocg, 2ocg+1}
        const int pr0 = pairg, pr1 = pairg + 8;
        float2 b2v = __ldg((const float2*)b2 + ocg);
        u64 A[5], B[5], C[5], D[5];
        u64 bA = dup2(b2v.x), bB = dup2(b2v.y);
        #pragma unroll
        for (int o = 0; o < 5; o++) { A[o] = bA; B[o] = bB; C[o] = bA; D[o] = bB; }
        const float2* w2p = (const float2*)g_w2t;    // row = 32 float2
        #pragma unroll 2
        for (int icp = 0; icp < 16; icp++) {
            const int ic = 2 * icp;
            float2 wa0 = __ldg(w2p + (ic * 3 + 0) * 32 + ocg);
            float2 wa1 = __ldg(w2p + (ic * 3 + 1) * 32 + ocg);
            float2 wa2 = __ldg(w2p + (ic * 3 + 2) * 32 + ocg);
            float2 wb0 = __ldg(w2p + (ic * 3 + 3) * 32 + ocg);
            float2 wb1 = __ldg(w2p + (ic * 3 + 4) * 32 + ocg);
            float2 wb2 = __ldg(w2p + (ic * 3 + 5) * 32 + ocg);
            u64 a0 = dup2(wa0.x), a1 = dup2(wa1.x), a2 = dup2(wa2.x);   // ic,  oc0
            u64 b0 = dup2(wa0.y), b1v = dup2(wa1.y), b2w = dup2(wa2.y); // ic,  oc1
            u64 c0 = dup2(wb0.x), c1 = dup2(wb1.x), c2 = dup2(wb2.x);   // ic+1,oc0
            u64 d0 = dup2(wb0.y), d1 = dup2(wb1.y), d2 = dup2(wb2.y);   // ic+1,oc1
            {   // pair pr0 -> A,B
                const float* hb = sm + H1P_OFF + pr0 * 704 + ic * 2;
                ulonglong2 uv[11];
                #pragma unroll
                for (int p = 0; p < 11; p++)
                    uv[p] = *(const ulonglong2*)(hb + p * 64);
                #pragma unroll
                for (int o = 0; o < 5; o++) {
                    fma2(A[o], a0, uv[2*o].x);  fma2(A[o], a1, uv[2*o+1].x);  fma2(A[o], a2, uv[2*o+2].x);
                    fma2(A[o], c0, uv[2*o].y);  fma2(A[o], c1, uv[2*o+1].y);  fma2(A[o], c2, uv[2*o+2].y);
                    fma2(B[o], b0, uv[2*o].x);  fma2(B[o], b1v, uv[2*o+1].x); fma2(B[o], b2w, uv[2*o+2].x);
                    fma2(B[o], d0, uv[2*o].y);  fma2(B[o], d1, uv[2*o+1].y);  fma2(B[o], d2, uv[2*o+2].y);
                }
            }
            {   // pair pr1 -> C,D
                const float* hb = sm + H1P_OFF + pr1 * 704 + ic * 2;
                ulonglong2 uv[11];
                #pragma unroll
                for (int p = 0; p < 11; p++)
                    uv[p] = *(const ulonglong2*)(hb + p * 64);
                #pragma unroll
                for (int o = 0; o < 5; o++) {
                    fma2(C[o], a0, uv[2*o].x);  fma2(C[o], a1, uv[2*o+1].x);  fma2(C[o], a2, uv[2*o+2].x);
                    fma2(C[o], c0, uv[2*o].y);  fma2(C[o], c1, uv[2*o+1].y);  fma2(C[o], c2, uv[2*o+2].y);
                    fma2(D[o], b0, uv[2*o].x);  fma2(D[o], b1v, uv[2*o+1].x); fma2(D[o], b2w, uv[2*o+2].x);
                    fma2(D[o], d0, uv[2*o].y);  fma2(D[o], d1, uv[2*o+1].y);  fma2(D[o], d2, uv[2*o+2].y);
                }
            }
        }
        #pragma unroll
        for (int o = 0; o < 5; o++) {
            float2 v0 = unp2(A[o]), v1 = unp2(B[o]);
            *(float4*)(sm + H2P_OFF + (pr0 * 5 + o) * 128 + 4 * ocg) =
                make_float4(fmaxf(v0.x,0.f), fmaxf(v0.y,0.f), fmaxf(v1.x,0.f), fmaxf(v1.y,0.f));
            float2 v2 = unp2(C[o]), v3 = unp2(D[o]);
            *(float4*)(sm + H2P_OFF + (pr1 * 5 + o) * 128 + 4 * ocg) =
                make_float4(fmaxf(v2.x,0.f), fmaxf(v2.y,0.f), fmaxf(v3.x,0.f), fmaxf(v3.y,0.f));
        }
    }
    __syncthreads();

    // ---- conv3: 64->128, len 5 -> 3, stride 2. 2 oc x 4 pairs per thread;
    //      256 active threads; direct epilogue. ----
    {
        const int ocg = tid & 63, sg = tid >> 6;     // oc = {2ocg, 2ocg+1}, sg 0-3
        float2 b3v = __ldg((const float2*)b3 + ocg);
        u64 P[4][3], Q[4][3];
        {
            u64 bx = dup2(b3v.x), by = dup2(b3v.y);
            #pragma unroll
            for (int j = 0; j < 4; j++) {
                P[j][0] = bx; P[j][1] = bx; P[j][2] = bx;
                Q[j][0] = by; Q[j][1] = by; Q[j][2] = by;
            }
        }
        const float2* w3p = (const float2*)g_w3t;    // row = 64 float2
        #pragma unroll 2
        for (int icp = 0; icp < 32; icp++) {
            const int ic = 2 * icp;
            float2 wa0 = __ldg(w3p + (ic * 3 + 0) * 64 + ocg);
            float2 wa1 = __ldg(w3p + (ic * 3 + 1) * 64 + ocg);
            float2 wa2 = __ldg(w3p + (ic * 3 + 2) * 64 + ocg);
            float2 wb0 = __ldg(w3p + (ic * 3 + 3) * 64 + ocg);
            float2 wb1 = __ldg(w3p + (ic * 3 + 4) * 64 + ocg);
            float2 wb2 = __ldg(w3p + (ic * 3 + 5) * 64 + ocg);
            u64 da0 = dup2(wa0.x), da1 = dup2(wa1.x), da2 = dup2(wa2.x); // ic, oc0
            u64 db0 = dup2(wa0.y), db1 = dup2(wa1.y), db2 = dup2(wa2.y); // ic, oc1
            u64 dc0 = dup2(wb0.x), dc1 = dup2(wb1.x), dc2 = dup2(wb2.x); // ic+1, oc0
            u64 dd0 = dup2(wb0.y), dd1 = dup2(wb1.y), dd2 = dup2(wb2.y); // ic+1, oc1
            #pragma unroll
            for (int j = 0; j < 4; j++) {
                const int pr = 4 * sg + j;
                const float* hb = sm + H2P_OFF + (pr * 320 + ic) * 2;
                ulonglong2 u0 = *(const ulonglong2*)(hb);
                ulonglong2 u1 = *(const ulonglong2*)(hb + 128);
                ulonglong2 u2 = *(const ulonglong2*)(hb + 256);
                ulonglong2 u3 = *(const ulonglong2*)(hb + 384);
                ulonglong2 u4 = *(const ulonglong2*)(hb + 512);
                C3(P[j][0], P[j][1], P[j][2], da0, da1, da2, u0.x, u1.x, u2.x, u3.x, u4.x);
                C3(P[j][0], P[j][1], P[j][2], dc0, dc1, dc2, u0.y, u1.y, u2.y, u3.y, u4.y);
                C3(Q[j][0], Q[j][1], Q[j][2], db0, db1, db2, u0.x, u1.x, u2.x, u3.x, u4.x);
                C3(Q[j][0], Q[j][1], Q[j][2], dd0, dd1, dd2, u0.y, u1.y, u2.y, u3.y, u4.y);
            }
        }
        const int* vA = (const int*)(sm + VA_OFF);
        #pragma unroll
        for (int j = 0; j < 4; j++) {
            const int pr = 4 * sg + j;
            float2 v0 = unp2(P[j][0]), v1 = unp2(P[j][1]), v2 = unp2(P[j][2]);
            float2 w0 = unp2(Q[j][0]), w1 = unp2(Q[j][1]), w2 = unp2(Q[j][2]);
            float eX0 = (fmaxf(v0.x,0.f) + fmaxf(v1.x,0.f) + fmaxf(v2.x,0.f)) * (1.f/3.f);
            float eY0 = (fmaxf(v0.y,0.f) + fmaxf(v1.y,0.f) + fmaxf(v2.y,0.f)) * (1.f/3.f);
            float eX1 = (fmaxf(w0.x,0.f) + fmaxf(w1.x,0.f) + fmaxf(w2.x,0.f)) * (1.f/3.f);
            float eY1 = (fmaxf(w0.y,0.f) + fmaxf(w1.y,0.f) + fmaxf(w2.y,0.f)) * (1.f/3.f);
            int aa = 2 * pr;
            if (!vA[aa])     { eX0 = 0.f; eX1 = 0.f; }
            if (!vA[aa + 1]) { eY0 = 0.f; eY1 = 0.f; }
            int g0 = gbase + aa, g1 = g0 + 1;
            if (g0 & (AN - 1)) {
                int c = __ldg(&category[g0]);
                float2 te = __ldg((const float2*)type_emb + c * 64 + ocg);
                __stcs((float2*)(out + (size_t)g0 * 128 + 2 * ocg),
                       make_float2(eX0 + te.x, eX1 + te.y));
            }
            {
                int c = __ldg(&category[g1]);
                float2 te = __ldg((const float2*)type_emb + c * 64 + ocg);
                __stcs((float2*)(out + (size_t)g1 * 128 + 2 * ocg),
                       make_float2(eY0 + te.x, eY1 + te.y));
            }
        }
    }
}

// ---------------------------------------------------------------------------
extern "C" void kernel_launch(void* const* d_in, const int* in_sizes, int n_in,
                              void* d_out, int out_size) {
    const float* position  = (const float*)d_in[0];
    const float* heading   = (const float*)d_in[1];
    const float* velocity  = (const float*)d_in[2];
    const float* shp       = (const float*)d_in[3];
    const float* cur       = (const float*)d_in[4];
    const int*   category  = (const int*)d_in[5];
    const void*  vmask     = d_in[6];
    const float* w1        = (const float*)d_in[7];
    const float* b1        = (const float*)d_in[8];
    const float* w2        = (const float*)d_in[9];
    const float* b2        = (const float*)d_in[10];
    const float* w3        = (const float*)d_in[11];
    const float* b3        = (const float*)d_in[12];
    const float* se_w      = (const float*)d_in[13];
    const float* se_b      = (const float*)d_in[14];
    const float* pos_embed = (const float*)d_in[15];
    const float* query     = (const float*)d_in[16];
    const float* inW       = (const float*)d_in[17];
    const float* inB       = (const float*)d_in[18];
    const float* outW      = (const float*)d_in[19];
    const float* outB      = (const float*)d_in[20];
    const float* type_emb  = (const float*)d_in[n_in - 1];
    float* out = (float*)d_out;

    // idempotent, non-stream API; safe under graph capture
    cudaFuncSetAttribute(main_kernel, cudaFuncAttributeMaxDynamicSharedMemorySize,
                         SMEM_FLOATS * (int)sizeof(float));

    prep_kernel<<<192, 256>>>((const unsigned char*)vmask, w1, w2, w3, inW, outW);

    // one merged launch: ego (blocks 0..255) + agent tiles (256..4351)
    main_kernel<<<EGO_BLKS + BN * AN / AG, NTHR, SMEM_FLOATS * sizeof(float)>>>(
        position, heading, velocity, shp, category, vmask,
        b1, b2, b3, type_emb, out,
        cur, se_w, se_b, pos_embed, query, inB, outB);
}

// round 16
// speedup vs baseline: 1.2460x; 1.0189x over previous
#include <cuda_runtime.h>
#include <math.h>

// Problem constants
#define BN 256
#define AN 512
#define TT 21
#define AG 32      // agents per block (16 pairs)
#define NTHR 256
#define EGO_BLKS 256

__device__ int g_mask_is_byte;
__device__ __align__(16) float g_w1q[32 * 28];     // [oc][k(27)+pad] conv1 weights
__device__ __align__(16) float4 g_w2q[16 * 3 * 32];// [icp][tp][ocg] tap-pair quads
__device__ __align__(16) float4 g_w3q[32 * 3 * 64];// [icp][tp][ocg] tap-pair quads
__device__ __align__(16) float g_inWt[128 * 384];  // [e][row] transposed in_proj_w
__device__ __align__(16) float g_outWt[128 * 128]; // [e][row] transposed out_proj_w

// ---------------------------------------------------------------------------
// f32x2 packed helpers (Blackwell dual-fp32 datapath)
// ---------------------------------------------------------------------------
typedef unsigned long long u64;

__device__ __forceinline__ u64 dup2(float a) {
    u64 d; asm("mov.b64 %0,{%1,%1};" : "=l"(d) : "f"(a)); return d;
}
__device__ __forceinline__ void fma2(u64& acc, u64 w, u64 x) {
    asm("fma.rn.f32x2 %0,%1,%2,%0;" : "+l"(acc) : "l"(w), "l"(x));
}
__device__ __forceinline__ float2 unp2(u64 v) {
    float a, b; asm("mov.b64 {%0,%1},%2;" : "=f"(a), "=f"(b) : "l"(v));
    return make_float2(a, b);
}

// conv3 tap pattern: o0: k1*x0+k2*x1 ; o1: k0*x1+k1*x2+k2*x3 ; o2: k0*x3+k1*x4
#define C3(s0, s1, s2, d0, d1, d2, X0, X1, X2, X3, X4) do { \
    fma2(s0, d1, X0); fma2(s0, d2, X1); \
    fma2(s1, d0, X1); fma2(s1, d1, X2); fma2(s1, d2, X3); \
    fma2(s2, d0, X3); fma2(s2, d1, X4); } while (0)

__device__ __forceinline__ int mask_at(const void* p, int idx, int isByte) {
    if (isByte) return ((const unsigned char*)p)[idx] != 0;
    return ((const int*)p)[idx] != 0;
}

// ---------------------------------------------------------------------------
// Prep: weight repacking + mask-dtype detect (block 0). ~4us.
// ---------------------------------------------------------------------------
__global__ void prep_kernel(const unsigned char* __restrict__ vm,
                            const float* __restrict__ w1,
                            const float* __restrict__ w2,
                            const float* __restrict__ w3,
                            const float* __restrict__ inW,
                            const float* __restrict__ outW) {
    int i = blockIdx.x * 256 + threadIdx.x;
    // conv1: [oc][28] padded row-contiguous
    if (i < 864)  { int oc = i / 27, k = i % 27; g_w1q[oc * 28 + k] = w1[oc * 27 + k]; }
    if (i < 32)   g_w1q[i * 28 + 27] = 0.f;
    // conv2 tap-pair quads: q(icp,tp)[ocg] = {t.oc0, t.oc1, t+1.oc0, t+1.oc1}, t = 6icp+2tp
    if (i < 1536) {
        int ocg = i & 31, tp = (i >> 5) % 3, icp = i / 96;
        int k0 = icp * 6 + 2 * tp;
        g_w2q[i] = make_float4(w2[(2 * ocg) * 96 + k0],     w2[(2 * ocg + 1) * 96 + k0],
                               w2[(2 * ocg) * 96 + k0 + 1], w2[(2 * ocg + 1) * 96 + k0 + 1]);
    }
    // conv3 tap-pair quads
    if (i < 6144) {
        int ocg = i & 63, tp = (i >> 6) % 3, icp = i / 192;
        int k0 = icp * 6 + 2 * tp;
        g_w3q[i] = make_float4(w3[(2 * ocg) * 192 + k0],     w3[(2 * ocg + 1) * 192 + k0],
                               w3[(2 * ocg) * 192 + k0 + 1], w3[(2 * ocg + 1) * 192 + k0 + 1]);
    }
    if (i < 49152) { int row = i / 128, e = i % 128; g_inWt[e * 384 + row] = inW[i]; }
    if (i < 16384) { int row = i / 128, e = i % 128; g_outWt[e * 128 + row] = outW[i]; }
    if (blockIdx.x == 0) {
        __shared__ int found;
        if (threadIdx.x == 0) found = 0;
        __syncthreads();
        int local = 0;
        for (int j = 0; j < 8; j++) local |= vm[4 * (threadIdx.x * 8 + j) + 1];
        if (local) atomicOr(&found, 1);
        __syncthreads();
        if (threadIdx.x == 0) g_mask_is_byte = found ? 1 : 0;
    }
}

// smem layout (float offsets), all pair-packed float2 (.x even agent, .y odd)
#define XSP_OFF 0        // 16 pairs * 9 ch * 22 t * 2      = 6336  (t20,21 pad)
#define H1P_OFF 6336     // 16 * 11 pos * 32 ic * 2 (posmaj)= 11264 (p10 pad row)
#define H2P_OFF 17600    // 16 * 5 pos * 64 ic * 2 (posmaj) = 10240 (no pad)
#define VA_OFF  27840    // 32 ints
#define SMEM_FLOATS 27872

// ego overlay offsets (within the same dynamic smem; ego uses 2584 floats)
#define EG_XE 0
#define EG_QS 768
#define EG_KS 896
#define EG_VS 1664
#define EG_AT 2432
#define EG_OS 2456

// ---------------------------------------------------------------------------
// Merged kernel: blocks 0..255 = ego attention; blocks 256.. = agent tiles
// (32 agents each). No static smem.
// ---------------------------------------------------------------------------
__global__ __launch_bounds__(NTHR, 2) void main_kernel(
    const float* __restrict__ position, const float* __restrict__ heading,
    const float* __restrict__ velocity, const float* __restrict__ shp,
    const int* __restrict__ category, const void* __restrict__ vmask,
    const float* __restrict__ b1, const float* __restrict__ b2,
    const float* __restrict__ b3,
    const float* __restrict__ type_emb, float* __restrict__ out,
    const float* __restrict__ cur,
    const float* __restrict__ se_w, const float* __restrict__ se_b,
    const float* __restrict__ pos_embed, const float* __restrict__ query,
    const float* __restrict__ inB, const float* __restrict__ outB)
{
    extern __shared__ float sm[];
    const int tid = threadIdx.x;

    if (blockIdx.x < EGO_BLKS) {
        // ================= ego cross-attention (128 threads) ================
        if (tid >= 128) return;
        const int d = tid;
        const int b = blockIdx.x;
        float* xe = sm + EG_XE;
        float* qs = sm + EG_QS;
        float* ks = sm + EG_KS;
        float* vs = sm + EG_VS;
        float* att = sm + EG_AT;
        float* os = sm + EG_OS;
        #pragma unroll
        for (int s = 0; s < 6; s++) {
            float e = __ldg(&cur[b * 6 + s]);
            xe[s * 128 + d] = e * se_w[s * 128 + d] + se_b[s * 128 + d] + pos_embed[s * 128 + d];
        }
        {
            float acc = inB[d];
            for (int e = 0; e < 128; e++)
                acc += __ldg(&query[e]) * __ldg(&g_inWt[e * 384 + d]);
            qs[d] = acc;
        }
        __syncthreads();
        {
            float ak[6], av[6];
            float bk = inB[128 + d], bvv = inB[256 + d];
            #pragma unroll
            for (int s = 0; s < 6; s++) { ak[s] = bk; av[s] = bvv; }
            for (int e = 0; e < 128; e++) {
                float wkv = __ldg(&g_inWt[e * 384 + 128 + d]);   // Wk[d][e]
                float wvv = __ldg(&g_inWt[e * 384 + 256 + d]);   // Wv[d][e]
                #pragma unroll
                for (int s = 0; s < 6; s++) {
                    float x = xe[s * 128 + e];
                    ak[s] += wkv * x;
                    av[s] += wvv * x;
                }
            }
            #pragma unroll
            for (int s = 0; s < 6; s++) { ks[s * 128 + d] = ak[s]; vs[s * 128 + d] = av[s]; }
        }
        __syncthreads();
        if (d < 4) {
            int h = d;
            float sc[6], mx = -1e30f;
            #pragma unroll
            for (int s = 0; s < 6; s++) {
                float acc = 0.f;
                #pragma unroll
                for (int j = 0; j < 32; j++) acc += qs[h * 32 + j] * ks[s * 128 + h * 32 + j];
                sc[s] = acc * 0.17677669529663687f;  // 1/sqrt(32)
                mx = fmaxf(mx, sc[s]);
            }
            float sum = 0.f;
            #pragma unroll
            for (int s = 0; s < 6; s++) { sc[s] = expf(sc[s] - mx); sum += sc[s]; }
            float inv = 1.f / sum;
            #pragma unroll
            for (int s = 0; s < 6; s++) att[h * 6 + s] = sc[s] * inv;
        }
        __syncthreads();
        {
            int h = d >> 5;
            float o = 0.f;
            #pragma unroll
            for (int s = 0; s < 6; s++) o += att[h * 6 + s] * vs[s * 128 + d];
            os[d] = o;
        }
        __syncthreads();
        {
            float acc = outB[d];
            for (int e = 0; e < 128; e++)
                acc += os[e] * __ldg(&g_outWt[e * 128 + d]);     // outW[d][e]
            int c0 = __ldg(&category[b * AN]);
            out[(size_t)b * AN * 128 + d] = acc + type_emb[c0 * 128 + d];
        }
        return;
    }

    // ======================= agent encoder tile (32 agents) =================
    const int gbase = (blockIdx.x - EGO_BLKS) * AG;
    const int isByte = g_mask_is_byte;

    // ---- targeted pad zeroing ----
    for (int i = tid; i < 144; i += NTHR) {      // XSP t20,t21 per (pair,ch)
        int pair = i / 9, ch = i % 9;
        float* p = sm + XSP_OFF + pair * 396 + ch * 44 + 40;
        p[0] = 0.f; p[1] = 0.f; p[2] = 0.f; p[3] = 0.f;
    }
    for (int i = tid; i < 1024; i += NTHR) {     // H1 pad row p=10
        int pair = i >> 6, j = i & 63;
        sm[H1P_OFF + (pair * 11 + 10) * 64 + j] = 0.f;
    }
    if (tid < AG) {
        int g = gbase + tid;
        int any = 0;
        for (int t = 0; t < TT; t++) any |= mask_at(vmask, g * TT + t, isByte);
        ((int*)(sm + VA_OFF))[tid] = any;
    }

    // ---- features: 9 channels x 20 timesteps per agent, pair-packed ----
    for (int idx = tid; idx < AG * 20; idx += NTHR) {
        int a = idx / 20, t = idx % 20;
        int g = gbase + a;
        int pair = a >> 1, lane = a & 1;
        const float2* pf = (const float2*)(position + (size_t)g * 42);
        const float2* vf = (const float2*)(velocity + (size_t)g * 42);
        const float2* sf = (const float2*)(shp      + (size_t)g * 42);
        const float*  hh = heading + (size_t)g * 21;
        int m0 = mask_at(vmask, g * 21 + t,     isByte);
        int m1 = mask_at(vmask, g * 21 + t + 1, isByte);
        float fm = (m0 & m1) ? 1.f : 0.f;
        float2 pa = __ldcs(pf + t), pb = __ldcs(pf + t + 1);
        float2 va = __ldcs(vf + t), vb = __ldcs(vf + t + 1);
        float2 sb = __ldcs(sf + t + 1);
        float h0 = __ldcs(&hh[t]), h1 = __ldcs(&hh[t + 1]);
        float dx  = fm * (pb.x - pa.x);
        float dy  = fm * (pb.y - pa.y);
        float dvx = fm * (vb.x - va.x);
        float dvy = fm * (vb.y - va.y);
        float dh  = fm * (h1 - h0);
        float sv, cv;
        __sincosf(dh, &sv, &cv);     // |dh| small; abs err ~4e-7 << 1e-3 budget
        float* xr = sm + XSP_OFF + (pair * 9 * 22 + t) * 2 + lane;
        xr[0 * 44] = dx;   xr[1 * 44] = dy;
        xr[2 * 44] = dvx;  xr[3 * 44] = dvy;
        xr[4 * 44] = cv;   xr[5 * 44] = sv;
        xr[6 * 44] = sb.x; xr[7 * 44] = sb.y;
        xr[8 * 44] = fm;
    }
    __syncthreads();

    // ---- conv1: 9->32, len 20 -> 10, stride 2, relu.
    //      (oc, 2 sequential pairs)/thread; weights via 7 LDG.128. ----
    {
        const int oc = tid & 31, pair0 = tid >> 5;
        float wr[28];
        {
            const float4* wq = (const float4*)(g_w1q + oc * 28);
            #pragma unroll
            for (int q = 0; q < 7; q++) {
                float4 v = __ldg(wq + q);
                wr[4 * q + 0] = v.x; wr[4 * q + 1] = v.y;
                wr[4 * q + 2] = v.z; wr[4 * q + 3] = v.w;
            }
        }
        u64 bv = dup2(__ldg(&b1[oc]));
        #pragma unroll
        for (int pass = 0; pass < 2; pass++) {
            const int pair = pair0 + 8 * pass;
            u64 acc[10];
            #pragma unroll
            for (int o = 0; o < 10; o++) acc[o] = bv;
            #pragma unroll
            for (int ic = 0; ic < 9; ic++) {
                const ulonglong2* xv = (const ulonglong2*)(sm + XSP_OFF + (pair * 9 + ic) * 44);
                u64 d0 = dup2(wr[ic * 3 + 0]);
                u64 d1 = dup2(wr[ic * 3 + 1]);
                u64 d2 = dup2(wr[ic * 3 + 2]);
                {   // t = 0..11 -> outputs o = 0..4
                    ulonglong2 v0 = xv[0], v1 = xv[1], v2 = xv[2],
                               v3 = xv[3], v4 = xv[4], v5 = xv[5];
                    u64 x[12] = {v0.x, v0.y, v1.x, v1.y, v2.x, v2.y,
                                 v3.x, v3.y, v4.x, v4.y, v5.x, v5.y};
                    #pragma unroll
                    for (int o = 0; o < 5; o++) {
                        fma2(acc[o], d0, x[2 * o]);
                        fma2(acc[o], d1, x[2 * o + 1]);
                        fma2(acc[o], d2, x[2 * o + 2]);
                    }
                }
                {   // t = 10..21 -> outputs o = 5..9 (t20 = zeroed pad)
                    ulonglong2 v0 = xv[5], v1 = xv[6], v2 = xv[7],
                               v3 = xv[8], v4 = xv[9], v5 = xv[10];
                    u64 x[12] = {v0.x, v0.y, v1.x, v1.y, v2.x, v2.y,
                                 v3.x, v3.y, v4.x, v4.y, v5.x, v5.y};
                    #pragma unroll
                    for (int o = 5; o < 10; o++) {
                        int q = 2 * o - 10;
                        fma2(acc[o], d0, x[q]);
                        fma2(acc[o], d1, x[q + 1]);
                        fma2(acc[o], d2, x[q + 2]);
                    }
                }
            }
            #pragma unroll
            for (int o = 0; o < 10; o++) {
                float2 v = unp2(acc[o]);
                *(float2*)(sm + H1P_OFF + ((pair * 11 + o) * 32 + oc) * 2) =
                    make_float2(fmaxf(v.x, 0.f), fmaxf(v.y, 0.f));
            }
        }
    }
    __syncthreads();

    // ---- conv2: 32->64, len 10 -> 5, stride 2, relu.
    //      2 oc x 2 pairs per thread; weights via 3 LDG.128 per icp. ----
    {
        const int ocg = tid & 31, pairg = tid >> 5;   // oc = {2ocg, 2ocg+1}
        const int pr0 = pairg, pr1 = pairg + 8;
        float2 b2v = __ldg((const float2*)b2 + ocg);
        u64 A[5], B[5], C[5], D[5];
        u64 bA = dup2(b2v.x), bB = dup2(b2v.y);
        #pragma unroll
        for (int o = 0; o < 5; o++) { A[o] = bA; B[o] = bB; C[o] = bA; D[o] = bB; }
        #pragma unroll 2
        for (int icp = 0; icp < 16; icp++) {
            float4 q0 = __ldg(g_w2q + (icp * 3 + 0) * 32 + ocg);
            float4 q1 = __ldg(g_w2q + (icp * 3 + 1) * 32 + ocg);
            float4 q2 = __ldg(g_w2q + (icp * 3 + 2) * 32 + ocg);
            u64 a0 = dup2(q0.x), b0  = dup2(q0.y), a1  = dup2(q0.z), b1v = dup2(q0.w);
            u64 a2 = dup2(q1.x), b2w = dup2(q1.y), c0  = dup2(q1.z), d0  = dup2(q1.w);
            u64 c1 = dup2(q2.x), d1  = dup2(q2.y), c2  = dup2(q2.z), d2  = dup2(q2.w);
            const int ic = 2 * icp;
            {   // pair pr0 -> A,B
                const float* hb = sm + H1P_OFF + pr0 * 704 + ic * 2;
                ulonglong2 uv[11];
                #pragma unroll
                for (int p = 0; p < 11; p++)
                    uv[p] = *(const ulonglong2*)(hb + p * 64);
                #pragma unroll
                for (int o = 0; o < 5; o++) {
                    fma2(A[o], a0, uv[2*o].x);  fma2(A[o], a1, uv[2*o+1].x);  fma2(A[o], a2, uv[2*o+2].x);
                    fma2(A[o], c0, uv[2*o].y);  fma2(A[o], c1, uv[2*o+1].y);  fma2(A[o], c2, uv[2*o+2].y);
                    fma2(B[o], b0, uv[2*o].x);  fma2(B[o], b1v, uv[2*o+1].x); fma2(B[o], b2w, uv[2*o+2].x);
                    fma2(B[o], d0, uv[2*o].y);  fma2(B[o], d1, uv[2*o+1].y);  fma2(B[o], d2, uv[2*o+2].y);
                }
            }
            {   // pair pr1 -> C,D
                const float* hb = sm + H1P_OFF + pr1 * 704 + ic * 2;
                ulonglong2 uv[11];
                #pragma unroll
                for (int p = 0; p < 11; p++)
                    uv[p] = *(const ulonglong2*)(hb + p * 64);
                #pragma unroll
                for (int o = 0; o < 5; o++) {
                    fma2(C[o], a0, uv[2*o].x);  fma2(C[o], a1, uv[2*o+1].x);  fma2(C[o], a2, uv[2*o+2].x);
                    fma2(C[o], c0, uv[2*o].y);  fma2(C[o], c1, uv[2*o+1].y);  fma2(C[o], c2, uv[2*o+2].y);
                    fma2(D[o], b0, uv[2*o].x);  fma2(D[o], b1v, uv[2*o+1].x); fma2(D[o], b2w, uv[2*o+2].x);
                    fma2(D[o], d0, uv[2*o].y);  fma2(D[o], d1, uv[2*o+1].y);  fma2(D[o], d2, uv[2*o+2].y);
                }
            }
        }
        #pragma unroll
        for (int o = 0; o < 5; o++) {
            float2 v0 = unp2(A[o]), v1 = unp2(B[o]);
            *(float4*)(sm + H2P_OFF + (pr0 * 5 + o) * 128 + 4 * ocg) =
                make_float4(fmaxf(v0.x,0.f), fmaxf(v0.y,0.f), fmaxf(v1.x,0.f), fmaxf(v1.y,0.f));
            float2 v2 = unp2(C[o]), v3 = unp2(D[o]);
            *(float4*)(sm + H2P_OFF + (pr1 * 5 + o) * 128 + 4 * ocg) =
                make_float4(fmaxf(v2.x,0.f), fmaxf(v2.y,0.f), fmaxf(v3.x,0.f), fmaxf(v3.y,0.f));
        }
    }
    __syncthreads();

    // ---- conv3: 64->128, len 5 -> 3, stride 2. 2 oc x 4 pairs per thread;
    //      weights via 3 LDG.128 per icp; direct epilogue. ----
    {
        const int ocg = tid & 63, sg = tid >> 6;     // oc = {2ocg, 2ocg+1}, sg 0-3
        float2 b3v = __ldg((const float2*)b3 + ocg);
        u64 P[4][3], Q[4][3];
        {
            u64 bx = dup2(b3v.x), by = dup2(b3v.y);
            #pragma unroll
            for (int j = 0; j < 4; j++) {
                P[j][0] = bx; P[j][1] = bx; P[j][2] = bx;
                Q[j][0] = by; Q[j][1] = by; Q[j][2] = by;
            }
        }
        #pragma unroll 2
        for (int icp = 0; icp < 32; icp++) {
            float4 q0 = __ldg(g_w3q + (icp * 3 + 0) * 64 + ocg);
            float4 q1 = __ldg(g_w3q + (icp * 3 + 1) * 64 + ocg);
            float4 q2 = __ldg(g_w3q + (icp * 3 + 2) * 64 + ocg);
            u64 da0 = dup2(q0.x), db0 = dup2(q0.y), da1 = dup2(q0.z), db1 = dup2(q0.w);
            u64 da2 = dup2(q1.x), db2 = dup2(q1.y), dc0 = dup2(q1.z), dd0 = dup2(q1.w);
            u64 dc1 = dup2(q2.x), dd1 = dup2(q2.y), dc2 = dup2(q2.z), dd2 = dup2(q2.w);
            const int ic = 2 * icp;
            #pragma unroll
            for (int j = 0; j < 4; j++) {
                const int pr = 4 * sg + j;
                const float* hb = sm + H2P_OFF + (pr * 320 + ic) * 2;
                ulonglong2 u0 = *(const ulonglong2*)(hb);
                ulonglong2 u1 = *(const ulonglong2*)(hb + 128);
                ulonglong2 u2 = *(const ulonglong2*)(hb + 256);
                ulonglong2 u3 = *(const ulonglong2*)(hb + 384);
                ulonglong2 u4 = *(const ulonglong2*)(hb + 512);
                C3(P[j][0], P[j][1], P[j][2], da0, da1, da2, u0.x, u1.x, u2.x, u3.x, u4.x);
                C3(P[j][0], P[j][1], P[j][2], dc0, dc1, dc2, u0.y, u1.y, u2.y, u3.y, u4.y);
                C3(Q[j][0], Q[j][1], Q[j][2], db0, db1, db2, u0.x, u1.x, u2.x, u3.x, u4.x);
                C3(Q[j][0], Q[j][1], Q[j][2], dd0, dd1, dd2, u0.y, u1.y, u2.y, u3.y, u4.y);
            }
        }
        const int* vA = (const int*)(sm + VA_OFF);
        #pragma unroll
        for (int j = 0; j < 4; j++) {
            const int pr = 4 * sg + j;
            float2 v0 = unp2(P[j][0]), v1 = unp2(P[j][1]), v2 = unp2(P[j][2]);
            float2 w0 = unp2(Q[j][0]), w1 = unp2(Q[j][1]), w2 = unp2(Q[j][2]);
            float eX0 = (fmaxf(v0.x,0.f) + fmaxf(v1.x,0.f) + fmaxf(v2.x,0.f)) * (1.f/3.f);
            float eY0 = (fmaxf(v0.y,0.f) + fmaxf(v1.y,0.f) + fmaxf(v2.y,0.f)) * (1.f/3.f);
            float eX1 = (fmaxf(w0.x,0.f) + fmaxf(w1.x,0.f) + fmaxf(w2.x,0.f)) * (1.f/3.f);
            float eY1 = (fmaxf(w0.y,0.f) + fmaxf(w1.y,0.f) + fmaxf(w2.y,0.f)) * (1.f/3.f);
            int aa = 2 * pr;
            if (!vA[aa])     { eX0 = 0.f; eX1 = 0.f; }
            if (!vA[aa + 1]) { eY0 = 0.f; eY1 = 0.f; }
            int g0 = gbase + aa, g1 = g0 + 1;
            if (g0 & (AN - 1)) {
                int c = __ldg(&category[g0]);
                float2 te = __ldg((const float2*)type_emb + c * 64 + ocg);
                __stcs((float2*)(out + (size_t)g0 * 128 + 2 * ocg),
                       make_float2(eX0 + te.x, eX1 + te.y));
            }
            {
                int c = __ldg(&category[g1]);
                float2 te = __ldg((const float2*)type_emb + c * 64 + ocg);
                __stcs((float2*)(out + (size_t)g1 * 128 + 2 * ocg),
                       make_float2(eY0 + te.x, eY1 + te.y));
            }
        }
    }
}

// ---------------------------------------------------------------------------
extern "C" void kernel_launch(void* const* d_in, const int* in_sizes, int n_in,
                              void* d_out, int out_size) {
    const float* position  = (const float*)d_in[0];
    const float* heading   = (const float*)d_in[1];
    const float* velocity  = (const float*)d_in[2];
    const float* shp       = (const float*)d_in[3];
    const float* cur       = (const float*)d_in[4];
    const int*   category  = (const int*)d_in[5];
    const void*  vmask     = d_in[6];
    const float* w1        = (const float*)d_in[7];
    const float* b1        = (const float*)d_in[8];
    const float* w2        = (const float*)d_in[9];
    const float* b2        = (const float*)d_in[10];
    const float* w3        = (const float*)d_in[11];
    const float* b3        = (const float*)d_in[12];
    const float* se_w      = (const float*)d_in[13];
    const float* se_b      = (const float*)d_in[14];
    const float* pos_embed = (const float*)d_in[15];
    const float* query     = (const float*)d_in[16];
    const float* inW       = (const float*)d_in[17];
    const float* inB       = (const float*)d_in[18];
    const float* outW      = (const float*)d_in[19];
    const float* outB      = (const float*)d_in[20];
    const float* type_emb  = (const float*)d_in[n_in - 1];
    float* out = (float*)d_out;

    // idempotent, non-stream API; safe under graph capture
    cudaFuncSetAttribute(main_kernel, cudaFuncAttributeMaxDynamicSharedMemorySize,
                         SMEM_FLOATS * (int)sizeof(float));

    prep_kernel<<<192, 256>>>((const unsigned char*)vmask, w1, w2, w3, inW, outW);

    // one merged launch: ego (blocks 0..255) + agent tiles (256..4351)
    main_kernel<<<EGO_BLKS + BN * AN / AG, NTHR, SMEM_FLOATS * sizeof(float)>>>(
        position, heading, velocity, shp, category, vmask,
        b1, b2, b3, type_emb, out,
        cur, se_w, se_b, pos_embed, query, inB, outB);
}